// round 1
// baseline (speedup 1.0000x reference)
#include <cuda_runtime.h>
#include <cuda_bf16.h>

// Problem constants
#define VOCAB 32000
#define EMB   512
#define HID   1024
#define CTXD  2048
#define BATCH 64
#define TSTEPS 64
#define LCTX  64
#define XDIM  (EMB + CTXD)   // 2560
#define G3H   (3 * HID)      // 3072

// Scratch (device globals; no allocation allowed)
__device__ float g_ctxW[BATCH * LCTX * HID];   // 16.8 MB: ctx @ W_a^T  [B,L,H]
__device__ float g_X[BATCH * XDIM];            // [emb_t, c_t] per batch
__device__ float g_h[BATCH * HID];             // recurrent state
__device__ float g_gx[BATCH * G3H];
__device__ float g_gh[BATCH * G3H];

// ---------------------------------------------------------------------------
// Tiled fp32 GEMM: C[m0:m0+64, n0:n0+NT] = A[m,:K] @ B[n,:K]^T (+ bias)
// A row-major [M,K] lda=K, B row-major [N,K] (i.e. transposed op), 256 threads.
// ---------------------------------------------------------------------------
template<int NT, int MR, int NR>
__device__ __forceinline__ void gemm_tile(
    const float* __restrict__ A, int lda, int K,
    const float* __restrict__ B,
    const float* __restrict__ bias,
    float* __restrict__ C, int ldc,
    int m0, int n0, float* sm)
{
    constexpr int KT = 32;
    constexpr int TN = NT / NR;          // thread groups along n
    float* Xs = sm;                      // [KT][66] transposed A tile
    float* Ws = sm + KT * 66;            // [KT][66] transposed B tile

    const int tid = threadIdx.x;
    const int tm = tid / TN;             // covers 64 rows: tm*MR..
    const int tn = tid % TN;             // covers NT cols: tn*NR..

    float acc[MR][NR];
#pragma unroll
    for (int i = 0; i < MR; i++)
#pragma unroll
        for (int j = 0; j < NR; j++) acc[i][j] = 0.f;

    for (int k0 = 0; k0 < K; k0 += KT) {
        // Load A tile (64 x 32), store k-major with pad 66
#pragma unroll
        for (int idx = tid; idx < 64 * KT / 4; idx += 256) {
            int row = idx >> 3, kc = idx & 7;
            float4 v = *(const float4*)(A + (size_t)(m0 + row) * lda + k0 + kc * 4);
            Xs[(kc * 4 + 0) * 66 + row] = v.x;
            Xs[(kc * 4 + 1) * 66 + row] = v.y;
            Xs[(kc * 4 + 2) * 66 + row] = v.z;
            Xs[(kc * 4 + 3) * 66 + row] = v.w;
        }
        // Load B tile (NT x 32), k-major
#pragma unroll
        for (int idx = tid; idx < NT * KT / 4; idx += 256) {
            int n = idx >> 3, kc = idx & 7;
            float4 v = *(const float4*)(B + (size_t)(n0 + n) * K + k0 + kc * 4);
            Ws[(kc * 4 + 0) * 66 + n] = v.x;
            Ws[(kc * 4 + 1) * 66 + n] = v.y;
            Ws[(kc * 4 + 2) * 66 + n] = v.z;
            Ws[(kc * 4 + 3) * 66 + n] = v.w;
        }
        __syncthreads();
#pragma unroll
        for (int kk = 0; kk < KT; kk++) {
            float a[MR], bb[NR];
#pragma unroll
            for (int i = 0; i < MR; i++) a[i] = Xs[kk * 66 + tm * MR + i];
#pragma unroll
            for (int j = 0; j < NR; j++) bb[j] = Ws[kk * 66 + tn * NR + j];
#pragma unroll
            for (int i = 0; i < MR; i++)
#pragma unroll
                for (int j = 0; j < NR; j++)
                    acc[i][j] = fmaf(a[i], bb[j], acc[i][j]);
        }
        __syncthreads();
    }

#pragma unroll
    for (int i = 0; i < MR; i++) {
        int m = m0 + tm * MR + i;
#pragma unroll
        for (int j = 0; j < NR; j++) {
            int n = n0 + tn * NR + j;
            float bv = bias ? bias[n] : 0.f;
            C[(size_t)m * ldc + n] = acc[i][j] + bv;
        }
    }
}

// ctxW precompute: [4096,1024] = ctx[4096,2048] @ W_a[1024,2048]^T
__global__ void k_ctxW(const float* __restrict__ ctx, const float* __restrict__ Wa)
{
    extern __shared__ float sm[];
    gemm_tile<64, 4, 4>(ctx, CTXD, CTXD, Wa, nullptr,
                        g_ctxW, HID, blockIdx.y * 64, blockIdx.x * 64, sm);
}

// Per-step gates: gx = X_ec @ W_ih^T + b_ih   (96 CTAs, NT=32, K=2560)
//                 gh = h    @ W_hh^T + b_hh   (48 CTAs, NT=64, K=1024)
__global__ void k_gates(const float* __restrict__ Wih, const float* __restrict__ Whh,
                        const float* __restrict__ bih, const float* __restrict__ bhh)
{
    extern __shared__ float sm[];
    int bx = blockIdx.x;
    if (bx < 96) {
        gemm_tile<32, 2, 4>(g_X, XDIM, XDIM, Wih, bih, g_gx, G3H, 0, bx * 32, sm);
    } else {
        gemm_tile<64, 4, 4>(g_h, HID, HID, Whh, bhh, g_gh, G3H, 0, (bx - 96) * 64, sm);
    }
}

// Fused: GRU update for step t (if t>=0), then attention + input build for t+1.
// One CTA per batch element, 256 threads.
__global__ void k_gru_att(int t,
                          const int* __restrict__ tgt,
                          const float* __restrict__ ctx,
                          const float* __restrict__ emb_table,
                          const int* __restrict__ ctx_lengths,
                          const float* __restrict__ h0,
                          float* __restrict__ out)
{
    __shared__ float h_s[HID];
    __shared__ float attn[LCTX];

    const int b = blockIdx.x;
    const int tid = threadIdx.x;

    if (t >= 0) {
        // GRU elementwise update
        for (int j = tid; j < HID; j += 256) {
            float gxr = g_gx[b * G3H + j];
            float gxz = g_gx[b * G3H + HID + j];
            float gxn = g_gx[b * G3H + 2 * HID + j];
            float ghr = g_gh[b * G3H + j];
            float ghz = g_gh[b * G3H + HID + j];
            float ghn = g_gh[b * G3H + 2 * HID + j];
            float r = 1.f / (1.f + __expf(-(gxr + ghr)));
            float z = 1.f / (1.f + __expf(-(gxz + ghz)));
            float n = tanhf(gxn + r * ghn);
            float h = (1.f - z) * n + z * g_h[b * HID + j];
            h_s[j] = h;
            g_h[b * HID + j] = h;
            out[((size_t)b * TSTEPS + t) * HID + j] = h;
            if (t == TSTEPS - 1)
                out[(size_t)BATCH * TSTEPS * HID + (size_t)b * HID + j] = h;
        }
    } else {
        // prologue: seed h from h0
        for (int j = tid; j < HID; j += 256) {
            float h = h0[b * HID + j];
            h_s[j] = h;
            g_h[b * HID + j] = h;
        }
    }
    __syncthreads();

    if (t == TSTEPS - 1) return;   // no attention needed after last step
    const int tstep = t + 1;

    // scores[l] = <h, ctxW[b,l,:]>  — one warp per l (8 warps round-robin)
    const int wid = tid >> 5, lane = tid & 31;
    for (int l = wid; l < LCTX; l += 8) {
        const float* cw = g_ctxW + ((size_t)b * LCTX + l) * HID;
        float s = 0.f;
#pragma unroll 4
        for (int i = lane; i < HID; i += 32) s += h_s[i] * cw[i];
#pragma unroll
        for (int off = 16; off > 0; off >>= 1)
            s += __shfl_xor_sync(0xffffffffu, s, off);
        if (lane == 0) attn[l] = s;
    }
    __syncthreads();

    // masked softmax over 64 positions (warp 0, 2 per lane)
    if (tid < 32) {
        int len = ctx_lengths[b];
        float s0 = (tid < len)      ? attn[tid]      : -1e9f;
        float s1 = (tid + 32 < len) ? attn[tid + 32] : -1e9f;
        float m = fmaxf(s0, s1);
#pragma unroll
        for (int off = 16; off > 0; off >>= 1)
            m = fmaxf(m, __shfl_xor_sync(0xffffffffu, m, off));
        float e0 = __expf(s0 - m), e1 = __expf(s1 - m);
        float ss = e0 + e1;
#pragma unroll
        for (int off = 16; off > 0; off >>= 1)
            ss += __shfl_xor_sync(0xffffffffu, ss, off);
        attn[tid]      = e0 / ss;
        attn[tid + 32] = e1 / ss;
    }
    __syncthreads();

    // c_t = attn @ ctx[b]  -> g_X[b, EMB : EMB+CTXD]
    const float* ctxb = ctx + (size_t)b * LCTX * CTXD;
    for (int c = tid; c < CTXD; c += 256) {
        float acc = 0.f;
#pragma unroll 8
        for (int l = 0; l < LCTX; l++)
            acc = fmaf(attn[l], ctxb[(size_t)l * CTXD + c], acc);
        g_X[b * XDIM + EMB + c] = acc;
    }

    // embedding gather for t+1 -> g_X[b, 0:EMB]
    int tok = tgt[b * TSTEPS + tstep];
    for (int i = tid; i < EMB; i += 256)
        g_X[b * XDIM + i] = emb_table[(size_t)tok * EMB + i];
}

extern "C" void kernel_launch(void* const* d_in, const int* in_sizes, int n_in,
                              void* d_out, int out_size)
{
    const int*   tgt     = (const int*)  d_in[0];
    const float* ctx     = (const float*)d_in[1];
    const float* h0      = (const float*)d_in[2];
    const int*   ctx_len = (const int*)  d_in[3];
    const float* emb     = (const float*)d_in[4];
    const float* Wa      = (const float*)d_in[5];
    const float* Wih     = (const float*)d_in[6];
    const float* Whh     = (const float*)d_in[7];
    const float* bih     = (const float*)d_in[8];
    const float* bhh     = (const float*)d_in[9];
    float* out = (float*)d_out;

    const size_t smem = 2 * 32 * 66 * sizeof(float);  // 16896 B

    // Precompute ctxW = ctx @ W_a^T   [4096, 1024]
    k_ctxW<<<dim3(16, 64), 256, smem>>>(ctx, Wa);

    // Prologue: seed h, attention for t=0 builds X
    k_gru_att<<<BATCH, 256>>>(-1, tgt, ctx, emb, ctx_len, h0, out);

    // Sequential decode
    for (int t = 0; t < TSTEPS; t++) {
        k_gates<<<144, 256, smem>>>(Wih, Whh, bih, bhh);
        k_gru_att<<<BATCH, 256>>>(t, tgt, ctx, emb, ctx_len, h0, out);
    }
}

// round 2
// speedup vs baseline: 3.0614x; 3.0614x over previous
#include <cuda_runtime.h>
#include <cuda_bf16.h>

#define VOCAB 32000
#define EMB   512
#define HID   1024
#define CTXD  2048
#define BATCH 64
#define TSTEPS 64
#define LCTX  64
#define XDIM  (EMB + CTXD)   // 2560
#define G3H   (3 * HID)      // 3072

// Device-global scratch (no allocation allowed)
__device__ float g_ctxW[BATCH * LCTX * HID];    // 16.8 MB  ctx @ Wa^T        [B*L, H]
__device__ float g_ctxP[BATCH * LCTX * G3H];    // 50.3 MB  ctx @ Wih_c^T     [B*L, 3H]
__device__ float g_gxe [BATCH * TSTEPS * G3H];  // 50.3 MB  emb @ Wih_e^T+bih [B*T, 3H]
__device__ float g_gxc [BATCH * G3H];           // attn-weighted ctxP
__device__ float g_gh2 [2][BATCH * G3H];        // K-split halves of h @ Whh^T
__device__ float g_h   [BATCH * HID];           // recurrent state
__device__ float g_scores[BATCH * LCTX];        // raw attention logits

// ---------------------------------------------------------------------------
// Big fp32 GEMM: C[128,128] tile = A[m,:K] @ B[n,:K]^T (+bias). 256 threads,
// 8x8 per thread, KT=32. Optional gather on A rows (embedding lookup).
// ---------------------------------------------------------------------------
template<bool GATHER>
__global__ __launch_bounds__(256, 2) void k_big_gemm(
    const float* __restrict__ A, const int* __restrict__ gidx, int lda,
    const float* __restrict__ B, int ldb, int K,
    const float* __restrict__ bias,
    float* __restrict__ C, int ldc)
{
    __shared__ __align__(16) float As[32 * 132];
    __shared__ __align__(16) float Bs[32 * 132];

    const int m0 = blockIdx.y * 128, n0 = blockIdx.x * 128;
    const int tid = threadIdx.x;
    const int tm = tid >> 4, tn = tid & 15;

    float acc[8][8];
#pragma unroll
    for (int i = 0; i < 8; i++)
#pragma unroll
        for (int j = 0; j < 8; j++) acc[i][j] = 0.f;

    for (int k0 = 0; k0 < K; k0 += 32) {
#pragma unroll
        for (int i = 0; i < 4; i++) {
            int idx = tid + i * 256;
            int row = idx >> 3, kc = idx & 7;
            const float* ar = GATHER ? A + (size_t)gidx[m0 + row] * lda
                                     : A + (size_t)(m0 + row) * lda;
            float4 v = *(const float4*)(ar + k0 + kc * 4);
            As[(kc * 4 + 0) * 132 + row] = v.x;
            As[(kc * 4 + 1) * 132 + row] = v.y;
            As[(kc * 4 + 2) * 132 + row] = v.z;
            As[(kc * 4 + 3) * 132 + row] = v.w;
            float4 w = *(const float4*)(B + (size_t)(n0 + row) * ldb + k0 + kc * 4);
            Bs[(kc * 4 + 0) * 132 + row] = w.x;
            Bs[(kc * 4 + 1) * 132 + row] = w.y;
            Bs[(kc * 4 + 2) * 132 + row] = w.z;
            Bs[(kc * 4 + 3) * 132 + row] = w.w;
        }
        __syncthreads();
#pragma unroll
        for (int kk = 0; kk < 32; kk++) {
            float a[8], b[8];
            *(float4*)(a)     = *(const float4*)&As[kk * 132 + tm * 8];
            *(float4*)(a + 4) = *(const float4*)&As[kk * 132 + tm * 8 + 4];
            *(float4*)(b)     = *(const float4*)&Bs[kk * 132 + tn * 8];
            *(float4*)(b + 4) = *(const float4*)&Bs[kk * 132 + tn * 8 + 4];
#pragma unroll
            for (int i = 0; i < 8; i++)
#pragma unroll
                for (int j = 0; j < 8; j++)
                    acc[i][j] = fmaf(a[i], b[j], acc[i][j]);
        }
        __syncthreads();
    }

#pragma unroll
    for (int i = 0; i < 8; i++) {
        int m = m0 + tm * 8 + i;
        float* crow = C + (size_t)m * ldc + n0 + tn * 8;
#pragma unroll
        for (int j4 = 0; j4 < 2; j4++) {
            float4 v;
            int nb = tn * 8 + j4 * 4;
            v.x = acc[i][j4 * 4 + 0] + (bias ? bias[n0 + nb + 0] : 0.f);
            v.y = acc[i][j4 * 4 + 1] + (bias ? bias[n0 + nb + 1] : 0.f);
            v.z = acc[i][j4 * 4 + 2] + (bias ? bias[n0 + nb + 2] : 0.f);
            v.w = acc[i][j4 * 4 + 3] + (bias ? bias[n0 + nb + 3] : 0.f);
            *(float4*)(crow + j4 * 4) = v;
        }
    }
}

// ---------------------------------------------------------------------------
// Small GEMM tile (for gh): C[64, NT] += A[64,:K] @ B[NT,:K]^T (+bias)
// ---------------------------------------------------------------------------
template<int NT, int MR, int NR>
__device__ __forceinline__ void gemm_tile(
    const float* __restrict__ A, int lda, int K,
    const float* __restrict__ B, int ldb,
    const float* __restrict__ bias,
    float* __restrict__ C, int ldc,
    int n0, float* sm)
{
    constexpr int KT = 32;
    constexpr int TN = NT / NR;
    float* Xs = sm;               // [KT][66]
    float* Ws = sm + KT * 66;     // [KT][66]

    const int tid = threadIdx.x;
    const int tm = tid / TN;
    const int tn = tid % TN;

    float acc[MR][NR];
#pragma unroll
    for (int i = 0; i < MR; i++)
#pragma unroll
        for (int j = 0; j < NR; j++) acc[i][j] = 0.f;

    for (int k0 = 0; k0 < K; k0 += KT) {
        for (int idx = tid; idx < 64 * KT / 4; idx += 256) {
            int row = idx >> 3, kc = idx & 7;
            float4 v = *(const float4*)(A + (size_t)row * lda + k0 + kc * 4);
            Xs[(kc * 4 + 0) * 66 + row] = v.x;
            Xs[(kc * 4 + 1) * 66 + row] = v.y;
            Xs[(kc * 4 + 2) * 66 + row] = v.z;
            Xs[(kc * 4 + 3) * 66 + row] = v.w;
        }
        for (int idx = tid; idx < NT * KT / 4; idx += 256) {
            int n = idx >> 3, kc = idx & 7;
            float4 v = *(const float4*)(B + (size_t)(n0 + n) * ldb + k0 + kc * 4);
            Ws[(kc * 4 + 0) * 66 + n] = v.x;
            Ws[(kc * 4 + 1) * 66 + n] = v.y;
            Ws[(kc * 4 + 2) * 66 + n] = v.z;
            Ws[(kc * 4 + 3) * 66 + n] = v.w;
        }
        __syncthreads();
#pragma unroll
        for (int kk = 0; kk < KT; kk++) {
            float a[MR], bb[NR];
#pragma unroll
            for (int i = 0; i < MR; i++) a[i] = Xs[kk * 66 + tm * MR + i];
#pragma unroll
            for (int j = 0; j < NR; j++) bb[j] = Ws[kk * 66 + tn * NR + j];
#pragma unroll
            for (int i = 0; i < MR; i++)
#pragma unroll
                for (int j = 0; j < NR; j++)
                    acc[i][j] = fmaf(a[i], bb[j], acc[i][j]);
        }
        __syncthreads();
    }

#pragma unroll
    for (int i = 0; i < MR; i++) {
        int m = tm * MR + i;
#pragma unroll
        for (int j = 0; j < NR; j++) {
            int n = n0 + tn * NR + j;
            C[(size_t)m * ldc + n] = acc[i][j] + (bias ? bias[n] : 0.f);
        }
    }
}

// ---------------------------------------------------------------------------
// K1: GRU elementwise update for step t (t>=0) or seed (t==-1),
//     then raw attention scores for step t+1. One CTA per batch.
// ---------------------------------------------------------------------------
__global__ void k_gru_scores(int t, const float* __restrict__ h0,
                             float* __restrict__ out)
{
    __shared__ __align__(16) float h_s[HID];
    const int b = blockIdx.x;
    const int tid = threadIdx.x;

    if (t >= 0) {
        const float* gxe = g_gxe + (size_t)(b * TSTEPS + t) * G3H;
        const float* gxc = g_gxc + (size_t)b * G3H;
        const float* gh0 = g_gh2[0] + (size_t)b * G3H;
        const float* gh1 = g_gh2[1] + (size_t)b * G3H;
        for (int j = tid; j < HID; j += 256) {
            float gxr = gxe[j]           + gxc[j];
            float gxz = gxe[HID + j]     + gxc[HID + j];
            float gxn = gxe[2 * HID + j] + gxc[2 * HID + j];
            float ghr = gh0[j]           + gh1[j];
            float ghz = gh0[HID + j]     + gh1[HID + j];
            float ghn = gh0[2 * HID + j] + gh1[2 * HID + j];
            float r = 1.f / (1.f + __expf(-(gxr + ghr)));
            float z = 1.f / (1.f + __expf(-(gxz + ghz)));
            float n = tanhf(gxn + r * ghn);
            float h = (1.f - z) * n + z * g_h[b * HID + j];
            h_s[j] = h;
            g_h[b * HID + j] = h;
            out[((size_t)b * TSTEPS + t) * HID + j] = h;
            if (t == TSTEPS - 1)
                out[(size_t)BATCH * TSTEPS * HID + (size_t)b * HID + j] = h;
        }
    } else {
        for (int j = tid; j < HID; j += 256) {
            float h = h0[b * HID + j];
            h_s[j] = h;
            g_h[b * HID + j] = h;
        }
    }
    __syncthreads();

    if (t == TSTEPS - 1) return;

    // scores[l] = <h, ctxW[b,l,:]> — one warp per l
    const int wid = tid >> 5, lane = tid & 31;
    const float4* h4 = (const float4*)h_s;
    for (int l = wid; l < LCTX; l += 8) {
        const float4* cw = (const float4*)(g_ctxW + ((size_t)b * LCTX + l) * HID);
        float s = 0.f;
#pragma unroll 8
        for (int i = lane; i < HID / 4; i += 32) {
            float4 hv = h4[i], cv = cw[i];
            s += hv.x * cv.x + hv.y * cv.y + hv.z * cv.z + hv.w * cv.w;
        }
#pragma unroll
        for (int off = 16; off > 0; off >>= 1)
            s += __shfl_xor_sync(0xffffffffu, s, off);
        if (lane == 0) g_scores[b * LCTX + l] = s;
    }
}

// ---------------------------------------------------------------------------
// K2: per step — CTAs [0,384): gh = h @ Whh^T (+bhh), K-split in 2 halves.
//               CTAs [384,512): softmax(scores) + gxc = attn @ ctxP.
// ---------------------------------------------------------------------------
__global__ void k_step2(const float* __restrict__ Whh,
                        const float* __restrict__ bhh,
                        const int* __restrict__ ctx_len)
{
    extern __shared__ float sm[];
    const int bx = blockIdx.x;
    const int tid = threadIdx.x;

    if (bx < 384) {
        int n0 = (bx % 192) * 16;
        int kh = bx / 192;
        gemm_tile<16, 2, 2>(g_h + kh * 512, HID, 512,
                            Whh + kh * 512, HID,
                            kh == 0 ? bhh : nullptr,
                            g_gh2[kh], G3H, n0, sm);
        return;
    }

    const int idx = bx - 384;
    const int b = idx >> 1, half = idx & 1;
    float* attn_s = sm;   // 64 floats

    if (tid < 32) {
        int len = ctx_len[b];
        float s0 = (tid < len)      ? g_scores[b * LCTX + tid]      : -1e9f;
        float s1 = (tid + 32 < len) ? g_scores[b * LCTX + tid + 32] : -1e9f;
        float m = fmaxf(s0, s1);
#pragma unroll
        for (int off = 16; off > 0; off >>= 1)
            m = fmaxf(m, __shfl_xor_sync(0xffffffffu, m, off));
        float e0 = __expf(s0 - m), e1 = __expf(s1 - m);
        float ss = e0 + e1;
#pragma unroll
        for (int off = 16; off > 0; off >>= 1)
            ss += __shfl_xor_sync(0xffffffffu, ss, off);
        attn_s[tid]      = e0 / ss;
        attn_s[tid + 32] = e1 / ss;
    }
    __syncthreads();

    // gxc[b, half*1536 + j*256 + tid] = sum_l attn[l] * ctxP[b,l, ...]
    float acc[6];
#pragma unroll
    for (int j = 0; j < 6; j++) acc[j] = 0.f;
    const float* base = g_ctxP + ((size_t)b * LCTX) * G3H + half * 1536 + tid;
#pragma unroll 4
    for (int l = 0; l < LCTX; l++) {
        float a = attn_s[l];
        const float* row = base + (size_t)l * G3H;
#pragma unroll
        for (int j = 0; j < 6; j++)
            acc[j] = fmaf(a, row[j * 256], acc[j]);
    }
    float* dst = g_gxc + (size_t)b * G3H + half * 1536 + tid;
#pragma unroll
    for (int j = 0; j < 6; j++) dst[j * 256] = acc[j];
}

extern "C" void kernel_launch(void* const* d_in, const int* in_sizes, int n_in,
                              void* d_out, int out_size)
{
    const int*   tgt     = (const int*)  d_in[0];
    const float* ctx     = (const float*)d_in[1];
    const float* h0      = (const float*)d_in[2];
    const int*   ctx_len = (const int*)  d_in[3];
    const float* emb     = (const float*)d_in[4];
    const float* Wa      = (const float*)d_in[5];
    const float* Wih     = (const float*)d_in[6];
    const float* Whh     = (const float*)d_in[7];
    const float* bih     = (const float*)d_in[8];
    const float* bhh     = (const float*)d_in[9];
    float* out = (float*)d_out;

    float* ctxW = nullptr; cudaGetSymbolAddress((void**)&ctxW, g_ctxW);
    float* ctxP = nullptr; cudaGetSymbolAddress((void**)&ctxP, g_ctxP);
    float* gxe  = nullptr; cudaGetSymbolAddress((void**)&gxe,  g_gxe);

    // Precompute (once, big GEMMs):
    // gx_emb[B*T,3H] = emb[tgt] @ Wih[:, :512]^T + b_ih
    k_big_gemm<true ><<<dim3(G3H / 128, BATCH * TSTEPS / 128), 256>>>(
        emb, tgt, EMB, Wih, XDIM, EMB, bih, gxe, G3H);
    // ctxW[B*L,H] = ctx @ Wa^T
    k_big_gemm<false><<<dim3(HID / 128, BATCH * LCTX / 128), 256>>>(
        ctx, nullptr, CTXD, Wa, CTXD, CTXD, nullptr, ctxW, HID);
    // ctxP[B*L,3H] = ctx @ Wih[:, 512:]^T
    k_big_gemm<false><<<dim3(G3H / 128, BATCH * LCTX / 128), 256>>>(
        ctx, nullptr, CTXD, Wih + EMB, XDIM, CTXD, nullptr, ctxP, G3H);

    const size_t smem2 = 2 * 32 * 66 * sizeof(float);  // 16896 B

    // Prologue: seed h = h0, compute scores for t=0
    k_gru_scores<<<BATCH, 256>>>(-1, h0, out);

    for (int t = 0; t < TSTEPS; t++) {
        k_step2<<<512, 256, smem2>>>(Whh, bhh, ctx_len);
        k_gru_scores<<<BATCH, 256>>>(t, h0, out);
    }
}

// round 7
// speedup vs baseline: 3.2625x; 1.0657x over previous
#include <cuda_runtime.h>
#include <cuda_bf16.h>
#include <cstdint>

#define VOCAB 32000
#define EMB   512
#define HID   1024
#define CTXD  2048
#define BATCH 64
#define TSTEPS 64
#define LCTX  64
#define XDIM  (EMB + CTXD)   // 2560
#define G3H   (3 * HID)      // 3072

// ---------------------------------------------------------------------------
// Device-global scratch
// ---------------------------------------------------------------------------
__device__ float g_ctxW[BATCH * LCTX * HID];    // ctx @ Wa^T        [B*L, H]
__device__ float g_ctxP[BATCH * LCTX * G3H];    // ctx @ Wih_c^T     [B*L, 3H]
__device__ float g_gxe [BATCH * TSTEPS * G3H];  // emb @ Wih_e^T+bih [B*T, 3H]
__device__ float g_gxc [BATCH * G3H];           // attn-weighted ctxP
__device__ float g_gh2 [2][BATCH * G3H];        // K-split halves of h @ Whh^T
__device__ float g_hbuf[2][BATCH * HID];        // ping-pong hidden state
__device__ float g_scores[BATCH * LCTX];        // raw attention logits

// ---------------------------------------------------------------------------
// f32x2 packed-FMA helpers (Blackwell sm_100+ base ISA)
// ---------------------------------------------------------------------------
typedef unsigned long long u64t;

__device__ __forceinline__ u64t pack2(float lo, float hi) {
    u64t r;
    asm("mov.b64 %0, {%1, %2};" : "=l"(r) : "f"(lo), "f"(hi));
    return r;
}
__device__ __forceinline__ u64t dup2(float x) { return pack2(x, x); }
__device__ __forceinline__ void fma2(u64t& d, u64t a, u64t b) {
    asm("fma.rn.f32x2 %0, %1, %2, %0;" : "+l"(d) : "l"(a), "l"(b));
}
__device__ __forceinline__ float2 unpack2(u64t v) {
    float lo, hi;
    asm("mov.b64 {%0, %1}, %2;" : "=f"(lo), "=f"(hi) : "l"(v));
    return make_float2(lo, hi);
}

// ---------------------------------------------------------------------------
// Big fp32 GEMM via packed f32x2 FMA: C[128,128] tile = A @ B^T (+bias).
// A[M,K] row-major (optional row gather), B[N,K] row-major. 256 threads,
// 8x8 outputs per thread (stored as 8x4 f32x2 pairs). Exact fp32 numerics.
// ---------------------------------------------------------------------------
template<bool GATHER>
__global__ __launch_bounds__(256, 2) void k_big_gemm(
    const float* __restrict__ A, const int* __restrict__ gidx, int lda,
    const float* __restrict__ B, int ldb, int K,
    const float* __restrict__ bias,
    float* __restrict__ C, int ldc)
{
    __shared__ __align__(16) float As[32 * 132];
    __shared__ __align__(16) float Bs[32 * 132];

    const int m0 = blockIdx.y * 128, n0 = blockIdx.x * 128;
    const int tid = threadIdx.x;
    const int tm = tid >> 4, tn = tid & 15;

    u64t acc[8][4];
#pragma unroll
    for (int i = 0; i < 8; i++)
#pragma unroll
        for (int j = 0; j < 4; j++) acc[i][j] = 0ull;

    for (int k0 = 0; k0 < K; k0 += 32) {
#pragma unroll
        for (int i = 0; i < 4; i++) {
            int idx = tid + i * 256;
            int row = idx >> 3, kc = idx & 7;
            const float* ar = GATHER ? A + (size_t)gidx[m0 + row] * lda
                                     : A + (size_t)(m0 + row) * lda;
            float4 v = *(const float4*)(ar + k0 + kc * 4);
            As[(kc * 4 + 0) * 132 + row] = v.x;
            As[(kc * 4 + 1) * 132 + row] = v.y;
            As[(kc * 4 + 2) * 132 + row] = v.z;
            As[(kc * 4 + 3) * 132 + row] = v.w;
            float4 w = *(const float4*)(B + (size_t)(n0 + row) * ldb + k0 + kc * 4);
            Bs[(kc * 4 + 0) * 132 + row] = w.x;
            Bs[(kc * 4 + 1) * 132 + row] = w.y;
            Bs[(kc * 4 + 2) * 132 + row] = w.z;
            Bs[(kc * 4 + 3) * 132 + row] = w.w;
        }
        __syncthreads();
#pragma unroll
        for (int kk = 0; kk < 32; kk++) {
            float a[8], b[8];
            *(float4*)(a)     = *(const float4*)&As[kk * 132 + tm * 8];
            *(float4*)(a + 4) = *(const float4*)&As[kk * 132 + tm * 8 + 4];
            *(float4*)(b)     = *(const float4*)&Bs[kk * 132 + tn * 8];
            *(float4*)(b + 4) = *(const float4*)&Bs[kk * 132 + tn * 8 + 4];
            u64t b2[4];
#pragma unroll
            for (int j = 0; j < 4; j++) b2[j] = pack2(b[2 * j], b[2 * j + 1]);
#pragma unroll
            for (int i = 0; i < 8; i++) {
                u64t a2 = dup2(a[i]);
#pragma unroll
                for (int j = 0; j < 4; j++)
                    fma2(acc[i][j], a2, b2[j]);
            }
        }
        __syncthreads();
    }

#pragma unroll
    for (int i = 0; i < 8; i++) {
        int m = m0 + tm * 8 + i;
        float* crow = C + (size_t)m * ldc + n0 + tn * 8;
#pragma unroll
        for (int j4 = 0; j4 < 2; j4++) {
            float2 p0 = unpack2(acc[i][j4 * 2 + 0]);
            float2 p1 = unpack2(acc[i][j4 * 2 + 1]);
            int nb = n0 + tn * 8 + j4 * 4;
            float4 v;
            v.x = p0.x + (bias ? bias[nb + 0] : 0.f);
            v.y = p0.y + (bias ? bias[nb + 1] : 0.f);
            v.z = p1.x + (bias ? bias[nb + 2] : 0.f);
            v.w = p1.y + (bias ? bias[nb + 3] : 0.f);
            *(float4*)(crow + j4 * 4) = v;
        }
    }
}

// ---------------------------------------------------------------------------
// Small fp32 GEMM tile for gh (scalar FFMA; proven correct)
// ---------------------------------------------------------------------------
template<int NT, int MR, int NR>
__device__ __forceinline__ void gemm_tile(
    const float* __restrict__ A, int lda, int K,
    const float* __restrict__ B, int ldb,
    const float* __restrict__ bias,
    float* __restrict__ C, int ldc,
    int n0, float* sm)
{
    constexpr int KT = 32;
    constexpr int TN = NT / NR;
    float* Xs = sm;
    float* Ws = sm + KT * 66;

    const int tid = threadIdx.x;
    const int tm = tid / TN;
    const int tn = tid % TN;

    float acc[MR][NR];
#pragma unroll
    for (int i = 0; i < MR; i++)
#pragma unroll
        for (int j = 0; j < NR; j++) acc[i][j] = 0.f;

    for (int k0 = 0; k0 < K; k0 += KT) {
        for (int idx = tid; idx < 64 * KT / 4; idx += 256) {
            int row = idx >> 3, kc = idx & 7;
            float4 v = *(const float4*)(A + (size_t)row * lda + k0 + kc * 4);
            Xs[(kc * 4 + 0) * 66 + row] = v.x;
            Xs[(kc * 4 + 1) * 66 + row] = v.y;
            Xs[(kc * 4 + 2) * 66 + row] = v.z;
            Xs[(kc * 4 + 3) * 66 + row] = v.w;
        }
        for (int idx = tid; idx < NT * KT / 4; idx += 256) {
            int n = idx >> 3, kc = idx & 7;
            float4 v = *(const float4*)(B + (size_t)(n0 + n) * ldb + k0 + kc * 4);
            Ws[(kc * 4 + 0) * 66 + n] = v.x;
            Ws[(kc * 4 + 1) * 66 + n] = v.y;
            Ws[(kc * 4 + 2) * 66 + n] = v.z;
            Ws[(kc * 4 + 3) * 66 + n] = v.w;
        }
        __syncthreads();
#pragma unroll
        for (int kk = 0; kk < KT; kk++) {
            float a[MR], bb[NR];
#pragma unroll
            for (int i = 0; i < MR; i++) a[i] = Xs[kk * 66 + tm * MR + i];
#pragma unroll
            for (int j = 0; j < NR; j++) bb[j] = Ws[kk * 66 + tn * NR + j];
#pragma unroll
            for (int i = 0; i < MR; i++)
#pragma unroll
                for (int j = 0; j < NR; j++)
                    acc[i][j] = fmaf(a[i], bb[j], acc[i][j]);
        }
        __syncthreads();
    }

#pragma unroll
    for (int i = 0; i < MR; i++) {
        int mm = tm * MR + i;
#pragma unroll
        for (int j = 0; j < NR; j++) {
            int n = n0 + tn * NR + j;
            C[(size_t)mm * ldc + n] = acc[i][j] + (bias ? bias[n] : 0.f);
        }
    }
}

// ---------------------------------------------------------------------------
// K1: GRU update for step t (or seed t==-1) + attention scores for t+1.
// grid = 512: CTA (b, slice). Reads h_in (stable), writes own 1/8 of h_out.
// ---------------------------------------------------------------------------
__global__ void k_gru_scores(int t,
                             const float* __restrict__ h_in,
                             float* __restrict__ h_out,
                             const float* __restrict__ h0,
                             float* __restrict__ out)
{
    __shared__ __align__(16) float h_s[HID];
    const int bx = blockIdx.x;
    const int b = bx >> 3, sl = bx & 7;
    const int tid = threadIdx.x;
    const int j = tid * 4;

    float hv[4];
    if (t >= 0) {
        const float* gxe = g_gxe + (size_t)(b * TSTEPS + t) * G3H;
        const float* gxc = g_gxc + (size_t)b * G3H;
        const float* gh0p = g_gh2[0] + (size_t)b * G3H;
        const float* gh1p = g_gh2[1] + (size_t)b * G3H;
        const float* hp = h_in + (size_t)b * HID;
#pragma unroll
        for (int q = 0; q < 4; q++) {
            int jj = j + q;
            float gxr = gxe[jj]           + gxc[jj];
            float gxz = gxe[HID + jj]     + gxc[HID + jj];
            float gxn = gxe[2 * HID + jj] + gxc[2 * HID + jj];
            float ghr = gh0p[jj]           + gh1p[jj];
            float ghz = gh0p[HID + jj]     + gh1p[HID + jj];
            float ghn = gh0p[2 * HID + jj] + gh1p[2 * HID + jj];
            float r = 1.f / (1.f + __expf(-(gxr + ghr)));
            float z = 1.f / (1.f + __expf(-(gxz + ghz)));
            float n = tanhf(gxn + r * ghn);
            hv[q] = (1.f - z) * n + z * hp[jj];
        }
    } else {
#pragma unroll
        for (int q = 0; q < 4; q++) hv[q] = h0[b * HID + j + q];
    }
    *(float4*)(h_s + j) = *(float4*)hv;

    if ((j >> 7) == sl) {
        *(float4*)(h_out + (size_t)b * HID + j) = *(float4*)hv;
        if (t >= 0) {
            *(float4*)(out + ((size_t)b * TSTEPS + t) * HID + j) = *(float4*)hv;
            if (t == TSTEPS - 1)
                *(float4*)(out + (size_t)BATCH * TSTEPS * HID + (size_t)b * HID + j) = *(float4*)hv;
        }
    }
    __syncthreads();

    if (t == TSTEPS - 1) return;

    const int wid = tid >> 5, lane = tid & 31;
    const int l = sl * 8 + wid;
    const float4* h4 = (const float4*)h_s;
    const float4* cw = (const float4*)(g_ctxW + ((size_t)b * LCTX + l) * HID);
    float s = 0.f;
#pragma unroll 8
    for (int i = lane; i < HID / 4; i += 32) {
        float4 a = h4[i], v = cw[i];
        s += a.x * v.x + a.y * v.y + a.z * v.z + a.w * v.w;
    }
#pragma unroll
    for (int off = 16; off > 0; off >>= 1)
        s += __shfl_xor_sync(0xffffffffu, s, off);
    if (lane == 0) g_scores[b * LCTX + l] = s;
}

// ---------------------------------------------------------------------------
// K2: gh GEMM (384 CTAs) + softmax+gxc (128 CTAs). Reads h_cur.
// ---------------------------------------------------------------------------
__global__ void k_step2(const float* __restrict__ h_cur,
                        const float* __restrict__ Whh,
                        const float* __restrict__ bhh,
                        const int* __restrict__ ctx_len)
{
    extern __shared__ float sm[];
    const int bx = blockIdx.x;
    const int tid = threadIdx.x;

    if (bx < 384) {
        int n0 = (bx % 192) * 16;
        int kh = bx / 192;
        gemm_tile<16, 2, 2>(h_cur + kh * 512, HID, 512,
                            Whh + kh * 512, HID,
                            kh == 0 ? bhh : nullptr,
                            g_gh2[kh], G3H, n0, sm);
        return;
    }

    const int idx = bx - 384;
    const int b = idx >> 1, half = idx & 1;
    float* attn_s = sm;

    if (tid < 32) {
        int len = ctx_len[b];
        float s0 = (tid < len)      ? g_scores[b * LCTX + tid]      : -1e9f;
        float s1 = (tid + 32 < len) ? g_scores[b * LCTX + tid + 32] : -1e9f;
        float m = fmaxf(s0, s1);
#pragma unroll
        for (int off = 16; off > 0; off >>= 1)
            m = fmaxf(m, __shfl_xor_sync(0xffffffffu, m, off));
        float e0 = __expf(s0 - m), e1 = __expf(s1 - m);
        float ss = e0 + e1;
#pragma unroll
        for (int off = 16; off > 0; off >>= 1)
            ss += __shfl_xor_sync(0xffffffffu, ss, off);
        attn_s[tid]      = e0 / ss;
        attn_s[tid + 32] = e1 / ss;
    }
    __syncthreads();

    float acc[6];
#pragma unroll
    for (int q = 0; q < 6; q++) acc[q] = 0.f;
    const float* base = g_ctxP + ((size_t)b * LCTX) * G3H + half * 1536 + tid;
#pragma unroll 4
    for (int l = 0; l < LCTX; l++) {
        float a = attn_s[l];
        const float* row = base + (size_t)l * G3H;
#pragma unroll
        for (int q = 0; q < 6; q++)
            acc[q] = fmaf(a, row[q * 256], acc[q]);
    }
    float* dst = g_gxc + (size_t)b * G3H + half * 1536 + tid;
#pragma unroll
    for (int q = 0; q < 6; q++) dst[q * 256] = acc[q];
}

// ---------------------------------------------------------------------------
extern "C" void kernel_launch(void* const* d_in, const int* in_sizes, int n_in,
                              void* d_out, int out_size)
{
    const int*   tgt     = (const int*)  d_in[0];
    const float* ctx     = (const float*)d_in[1];
    const float* h0      = (const float*)d_in[2];
    const int*   ctx_len = (const int*)  d_in[3];
    const float* emb     = (const float*)d_in[4];
    const float* Wa      = (const float*)d_in[5];
    const float* Wih     = (const float*)d_in[6];
    const float* Whh     = (const float*)d_in[7];
    const float* bih     = (const float*)d_in[8];
    const float* bhh     = (const float*)d_in[9];
    float* out = (float*)d_out;

    float* ctxW = nullptr; cudaGetSymbolAddress((void**)&ctxW, g_ctxW);
    float* ctxP = nullptr; cudaGetSymbolAddress((void**)&ctxP, g_ctxP);
    float* gxe  = nullptr; cudaGetSymbolAddress((void**)&gxe,  g_gxe);
    float* hbuf = nullptr; cudaGetSymbolAddress((void**)&hbuf, g_hbuf);
    float* hb[2] = { hbuf, hbuf + BATCH * HID };

    // Precompute GEMMs — exact fp32 via packed f32x2 FMA:
    // gxe[B*T,3H] = emb[tgt] @ Wih[:, :512]^T + bih
    k_big_gemm<true ><<<dim3(G3H / 128, BATCH * TSTEPS / 128), 256>>>(
        emb, tgt, EMB, Wih, XDIM, EMB, bih, gxe, G3H);
    // ctxW[B*L,H] = ctx @ Wa^T
    k_big_gemm<false><<<dim3(HID / 128, BATCH * LCTX / 128), 256>>>(
        ctx, nullptr, CTXD, Wa, CTXD, CTXD, nullptr, ctxW, HID);
    // ctxP[B*L,3H] = ctx @ Wih[:, 512:]^T
    k_big_gemm<false><<<dim3(G3H / 128, BATCH * LCTX / 128), 256>>>(
        ctx, nullptr, CTXD, Wih + EMB, XDIM, CTXD, nullptr, ctxP, G3H);

    const size_t smem2 = 2 * 32 * 66 * sizeof(float);

    // Prologue: seed h -> buf0, scores for t=0
    k_gru_scores<<<BATCH * 8, 256>>>(-1, nullptr, hb[0], h0, out);

    for (int t = 0; t < TSTEPS; t++) {
        const float* h_cur = hb[t & 1];
        float* h_nxt = hb[(t + 1) & 1];
        k_step2<<<512, 256, smem2>>>(h_cur, Whh, bhh, ctx_len);
        k_gru_scores<<<BATCH * 8, 256>>>(t, h_cur, h_nxt, h0, out);
    }
}

// round 9
// speedup vs baseline: 3.8025x; 1.1655x over previous
#include <cuda_runtime.h>
#include <cuda_bf16.h>
#include <cstdint>

#define VOCAB 32000
#define EMB   512
#define HID   1024
#define CTXD  2048
#define BATCH 64
#define TSTEPS 64
#define LCTX  64
#define XDIM  (EMB + CTXD)   // 2560
#define G3H   (3 * HID)      // 3072

// ---------------------------------------------------------------------------
// Device-global scratch
// ---------------------------------------------------------------------------
__device__ float g_ctxW[BATCH * LCTX * HID];    // ctx @ Wa^T        [B*L, H]
__device__ float g_ctxP[BATCH * LCTX * G3H];    // ctx @ Wih_c^T     [B*L, 3H]
__device__ float g_gxe [BATCH * TSTEPS * G3H];  // emb @ Wih_e^T+bih [B*T, 3H]
__device__ float g_gxc [BATCH * G3H];           // attn-weighted ctxP
__device__ float g_gh4 [4][BATCH * G3H];        // K-split quarters of h @ Whh^T
__device__ float g_h   [BATCH * HID];           // hidden state

// ---------------------------------------------------------------------------
// f32x2 packed-FMA helpers
// ---------------------------------------------------------------------------
typedef unsigned long long u64t;

__device__ __forceinline__ u64t pack2(float lo, float hi) {
    u64t r;
    asm("mov.b64 %0, {%1, %2};" : "=l"(r) : "f"(lo), "f"(hi));
    return r;
}
__device__ __forceinline__ u64t dup2(float x) { return pack2(x, x); }
__device__ __forceinline__ void fma2(u64t& d, u64t a, u64t b) {
    asm("fma.rn.f32x2 %0, %1, %2, %0;" : "+l"(d) : "l"(a), "l"(b));
}
__device__ __forceinline__ float2 unpack2(u64t v) {
    float lo, hi;
    asm("mov.b64 {%0, %1}, %2;" : "=f"(lo), "=f"(hi) : "l"(v));
    return make_float2(lo, hi);
}

// ---------------------------------------------------------------------------
// Big fp32 GEMM (precompute): C[128,128] tile = A @ B^T (+bias).
// Unchanged from R7 (passing).
// ---------------------------------------------------------------------------
template<bool GATHER>
__global__ __launch_bounds__(256, 2) void k_big_gemm(
    const float* __restrict__ A, const int* __restrict__ gidx, int lda,
    const float* __restrict__ B, int ldb, int K,
    const float* __restrict__ bias,
    float* __restrict__ C, int ldc)
{
    __shared__ __align__(16) float As[32 * 132];
    __shared__ __align__(16) float Bs[32 * 132];

    const int m0 = blockIdx.y * 128, n0 = blockIdx.x * 128;
    const int tid = threadIdx.x;
    const int tm = tid >> 4, tn = tid & 15;

    u64t acc[8][4];
#pragma unroll
    for (int i = 0; i < 8; i++)
#pragma unroll
        for (int j = 0; j < 4; j++) acc[i][j] = 0ull;

    for (int k0 = 0; k0 < K; k0 += 32) {
#pragma unroll
        for (int i = 0; i < 4; i++) {
            int idx = tid + i * 256;
            int row = idx >> 3, kc = idx & 7;
            const float* ar = GATHER ? A + (size_t)gidx[m0 + row] * lda
                                     : A + (size_t)(m0 + row) * lda;
            float4 v = *(const float4*)(ar + k0 + kc * 4);
            As[(kc * 4 + 0) * 132 + row] = v.x;
            As[(kc * 4 + 1) * 132 + row] = v.y;
            As[(kc * 4 + 2) * 132 + row] = v.z;
            As[(kc * 4 + 3) * 132 + row] = v.w;
            float4 w = *(const float4*)(B + (size_t)(n0 + row) * ldb + k0 + kc * 4);
            Bs[(kc * 4 + 0) * 132 + row] = w.x;
            Bs[(kc * 4 + 1) * 132 + row] = w.y;
            Bs[(kc * 4 + 2) * 132 + row] = w.z;
            Bs[(kc * 4 + 3) * 132 + row] = w.w;
        }
        __syncthreads();
#pragma unroll
        for (int kk = 0; kk < 32; kk++) {
            float a[8], b[8];
            *(float4*)(a)     = *(const float4*)&As[kk * 132 + tm * 8];
            *(float4*)(a + 4) = *(const float4*)&As[kk * 132 + tm * 8 + 4];
            *(float4*)(b)     = *(const float4*)&Bs[kk * 132 + tn * 8];
            *(float4*)(b + 4) = *(const float4*)&Bs[kk * 132 + tn * 8 + 4];
            u64t b2[4];
#pragma unroll
            for (int j = 0; j < 4; j++) b2[j] = pack2(b[2 * j], b[2 * j + 1]);
#pragma unroll
            for (int i = 0; i < 8; i++) {
                u64t a2 = dup2(a[i]);
#pragma unroll
                for (int j = 0; j < 4; j++)
                    fma2(acc[i][j], a2, b2[j]);
            }
        }
        __syncthreads();
    }

#pragma unroll
    for (int i = 0; i < 8; i++) {
        int m = m0 + tm * 8 + i;
        float* crow = C + (size_t)m * ldc + n0 + tn * 8;
#pragma unroll
        for (int j4 = 0; j4 < 2; j4++) {
            float2 p0 = unpack2(acc[i][j4 * 2 + 0]);
            float2 p1 = unpack2(acc[i][j4 * 2 + 1]);
            int nb = n0 + tn * 8 + j4 * 4;
            float4 v;
            v.x = p0.x + (bias ? bias[nb + 0] : 0.f);
            v.y = p0.y + (bias ? bias[nb + 1] : 0.f);
            v.z = p1.x + (bias ? bias[nb + 2] : 0.f);
            v.w = p1.y + (bias ? bias[nb + 3] : 0.f);
            *(float4*)(crow + j4 * 4) = v;
        }
    }
}

// ---------------------------------------------------------------------------
// K2: per step, 256 CTAs x 512 threads.
//  bx < 192: gh quarter-GEMM, smem row stride 68 floats (16B-aligned float4).
//  bx >= 192: attn CTA b: scores -> softmax -> gxc = attn @ ctxP.
// ---------------------------------------------------------------------------
#define PAD 68

__global__ void __launch_bounds__(512) k_step(
    const float* __restrict__ Whh,
    const float* __restrict__ bhh,
    const int* __restrict__ ctx_len)
{
    const int bx = blockIdx.x;
    const int tid = threadIdx.x;

    if (bx < 192) {
        __shared__ __align__(16) float Xs[32 * PAD];
        __shared__ __align__(16) float Ws[32 * PAD];
        const int kh = bx & 3;
        const int n0 = (bx >> 2) * 64;
        const float* A  = g_h + kh * 256;          // [64, 256] slice, lda = HID
        const float* Bw = Whh + kh * 256;          // row n: Bw + n*HID

        const int tm = tid >> 4, tn = tid & 15;    // tm in [0,32), tn in [0,16)
        const int lrow = tid >> 3, lkc = tid & 7;  // loader: row in [0,64), kc in [0,8)

        float acc[2][4];
#pragma unroll
        for (int i = 0; i < 2; i++)
#pragma unroll
            for (int j = 0; j < 4; j++) acc[i][j] = 0.f;

        for (int k0 = 0; k0 < 256; k0 += 32) {
            float4 v = *(const float4*)(A + (size_t)lrow * HID + k0 + lkc * 4);
            Xs[(lkc * 4 + 0) * PAD + lrow] = v.x;
            Xs[(lkc * 4 + 1) * PAD + lrow] = v.y;
            Xs[(lkc * 4 + 2) * PAD + lrow] = v.z;
            Xs[(lkc * 4 + 3) * PAD + lrow] = v.w;
            float4 w = *(const float4*)(Bw + (size_t)(n0 + lrow) * HID + k0 + lkc * 4);
            Ws[(lkc * 4 + 0) * PAD + lrow] = w.x;
            Ws[(lkc * 4 + 1) * PAD + lrow] = w.y;
            Ws[(lkc * 4 + 2) * PAD + lrow] = w.z;
            Ws[(lkc * 4 + 3) * PAD + lrow] = w.w;
            __syncthreads();
#pragma unroll
            for (int kk = 0; kk < 32; kk++) {
                float a0 = Xs[kk * PAD + tm * 2];
                float a1 = Xs[kk * PAD + tm * 2 + 1];
                float b[4];
                *(float4*)b = *(const float4*)&Ws[kk * PAD + tn * 4];
#pragma unroll
                for (int j = 0; j < 4; j++) {
                    acc[0][j] = fmaf(a0, b[j], acc[0][j]);
                    acc[1][j] = fmaf(a1, b[j], acc[1][j]);
                }
            }
            __syncthreads();
        }

        float* dst = g_gh4[kh];
#pragma unroll
        for (int i = 0; i < 2; i++) {
            int m = tm * 2 + i;
            int n = n0 + tn * 4;
            float4 v;
            v.x = acc[i][0]; v.y = acc[i][1]; v.z = acc[i][2]; v.w = acc[i][3];
            if (kh == 0) {
                v.x += bhh[n]; v.y += bhh[n + 1]; v.z += bhh[n + 2]; v.w += bhh[n + 3];
            }
            *(float4*)(dst + (size_t)m * G3H + n) = v;
        }
        return;
    }

    // ---- attention CTA ----
    const int b = bx - 192;
    __shared__ __align__(16) float h_s[HID];
    __shared__ float attn_s[LCTX];

    // load h (512 threads x 2 floats)
    ((float2*)h_s)[tid] = ((const float2*)(g_h + (size_t)b * HID))[tid];
    __syncthreads();

    // scores: 16 warps, 4 l's each
    const int w = tid >> 5, lane = tid & 31;
    const float4* h4 = (const float4*)h_s;
#pragma unroll
    for (int li = 0; li < 4; li++) {
        const int l = li * 16 + w;
        const float4* cw = (const float4*)(g_ctxW + ((size_t)b * LCTX + l) * HID);
        float s = 0.f;
#pragma unroll 8
        for (int i = lane; i < HID / 4; i += 32) {
            float4 a = h4[i], v = cw[i];
            s += a.x * v.x + a.y * v.y + a.z * v.z + a.w * v.w;
        }
#pragma unroll
        for (int off = 16; off > 0; off >>= 1)
            s += __shfl_xor_sync(0xffffffffu, s, off);
        if (lane == 0) attn_s[l] = s;
    }
    __syncthreads();

    // softmax (warp 0)
    if (tid < 32) {
        int len = ctx_len[b];
        float s0 = (tid < len)      ? attn_s[tid]      : -1e9f;
        float s1 = (tid + 32 < len) ? attn_s[tid + 32] : -1e9f;
        float m = fmaxf(s0, s1);
#pragma unroll
        for (int off = 16; off > 0; off >>= 1)
            m = fmaxf(m, __shfl_xor_sync(0xffffffffu, m, off));
        float e0 = __expf(s0 - m), e1 = __expf(s1 - m);
        float ss = e0 + e1;
#pragma unroll
        for (int off = 16; off > 0; off >>= 1)
            ss += __shfl_xor_sync(0xffffffffu, ss, off);
        attn_s[tid]      = e0 / ss;
        attn_s[tid + 32] = e1 / ss;
    }
    __syncthreads();

    // gxc[b, tid + q*512] = sum_l attn[l] * ctxP[b,l, tid + q*512]
    float acc[6];
#pragma unroll
    for (int q = 0; q < 6; q++) acc[q] = 0.f;
    const float* base = g_ctxP + ((size_t)b * LCTX) * G3H + tid;
#pragma unroll 4
    for (int l = 0; l < LCTX; l++) {
        float a = attn_s[l];
        const float* row = base + (size_t)l * G3H;
#pragma unroll
        for (int q = 0; q < 6; q++)
            acc[q] = fmaf(a, row[q * 512], acc[q]);
    }
    float* dst = g_gxc + (size_t)b * G3H + tid;
#pragma unroll
    for (int q = 0; q < 6; q++) dst[q * 512] = acc[q];
}

// ---------------------------------------------------------------------------
// K1: pure GRU elementwise. grid 64 CTAs x 256 threads, 4 h-elems per thread.
// ---------------------------------------------------------------------------
__global__ void k_gru(int t,
                      const float* __restrict__ h0,
                      float* __restrict__ out)
{
    const int b = blockIdx.x;
    const int j = threadIdx.x * 4;

    if (t < 0) {
        *(float4*)(g_h + (size_t)b * HID + j) =
            *(const float4*)(h0 + (size_t)b * HID + j);
        return;
    }

    const float* gxe = g_gxe + (size_t)(b * TSTEPS + t) * G3H;
    const float* gxc = g_gxc + (size_t)b * G3H;
    float* hp = g_h + (size_t)b * HID;

    float hv[4];
#pragma unroll
    for (int q = 0; q < 4; q++) {
        int jj = j + q;
        float gxr = gxe[jj]           + gxc[jj];
        float gxz = gxe[HID + jj]     + gxc[HID + jj];
        float gxn = gxe[2 * HID + jj] + gxc[2 * HID + jj];
        float ghr = 0.f, ghz = 0.f, ghn = 0.f;
#pragma unroll
        for (int kh = 0; kh < 4; kh++) {
            const float* gh = g_gh4[kh] + (size_t)b * G3H;
            ghr += gh[jj];
            ghz += gh[HID + jj];
            ghn += gh[2 * HID + jj];
        }
        float r = 1.f / (1.f + __expf(-(gxr + ghr)));
        float z = 1.f / (1.f + __expf(-(gxz + ghz)));
        float n = tanhf(gxn + r * ghn);
        hv[q] = (1.f - z) * n + z * hp[jj];
    }
    *(float4*)(hp + j) = *(float4*)hv;
    *(float4*)(out + ((size_t)b * TSTEPS + t) * HID + j) = *(float4*)hv;
    if (t == TSTEPS - 1)
        *(float4*)(out + (size_t)BATCH * TSTEPS * HID + (size_t)b * HID + j) = *(float4*)hv;
}

// ---------------------------------------------------------------------------
extern "C" void kernel_launch(void* const* d_in, const int* in_sizes, int n_in,
                              void* d_out, int out_size)
{
    const int*   tgt     = (const int*)  d_in[0];
    const float* ctx     = (const float*)d_in[1];
    const float* h0      = (const float*)d_in[2];
    const int*   ctx_len = (const int*)  d_in[3];
    const float* emb     = (const float*)d_in[4];
    const float* Wa      = (const float*)d_in[5];
    const float* Wih     = (const float*)d_in[6];
    const float* Whh     = (const float*)d_in[7];
    const float* bih     = (const float*)d_in[8];
    const float* bhh     = (const float*)d_in[9];
    float* out = (float*)d_out;

    float* ctxW = nullptr; cudaGetSymbolAddress((void**)&ctxW, g_ctxW);
    float* ctxP = nullptr; cudaGetSymbolAddress((void**)&ctxP, g_ctxP);
    float* gxe  = nullptr; cudaGetSymbolAddress((void**)&gxe,  g_gxe);

    // Precompute GEMMs (exact fp32):
    k_big_gemm<true ><<<dim3(G3H / 128, BATCH * TSTEPS / 128), 256>>>(
        emb, tgt, EMB, Wih, XDIM, EMB, bih, gxe, G3H);
    k_big_gemm<false><<<dim3(HID / 128, BATCH * LCTX / 128), 256>>>(
        ctx, nullptr, CTXD, Wa, CTXD, CTXD, nullptr, ctxW, HID);
    k_big_gemm<false><<<dim3(G3H / 128, BATCH * LCTX / 128), 256>>>(
        ctx, nullptr, CTXD, Wih + EMB, XDIM, CTXD, nullptr, ctxP, G3H);

    // Prologue: seed h = h0
    k_gru<<<BATCH, 256>>>(-1, h0, out);

    for (int t = 0; t < TSTEPS; t++) {
        k_step<<<256, 512>>>(Whh, bhh, ctx_len);   // scores/softmax/gxc + gh(t)
        k_gru<<<BATCH, 256>>>(t, h0, out);         // h(t) -> h(t+1), out
    }
}

// round 10
// speedup vs baseline: 3.9355x; 1.0350x over previous
#include <cuda_runtime.h>
#include <cuda_bf16.h>
#include <cstdint>

#define VOCAB 32000
#define EMB   512
#define HID   1024
#define CTXD  2048
#define BATCH 64
#define TSTEPS 64
#define LCTX  64
#define XDIM  (EMB + CTXD)   // 2560
#define G3H   (3 * HID)      // 3072

// ---------------------------------------------------------------------------
// Device-global scratch
// ---------------------------------------------------------------------------
__device__ float g_ctxW[BATCH * LCTX * HID];    // ctx @ Wa^T        [B*L, H]
__device__ float g_ctxP[BATCH * LCTX * G3H];    // ctx @ Wih_c^T     [B*L, 3H]
__device__ float g_gxe [BATCH * TSTEPS * G3H];  // emb @ Wih_e^T+bih [B*T, 3H]
__device__ float g_gxc [BATCH * G3H];           // attn-weighted ctxP
__device__ float g_gh4 [4][BATCH * G3H];        // K-split quarters of h @ Whh^T
__device__ float g_h   [BATCH * HID];           // hidden state

// bf16 3-way split buffers (hi / mid / lo)
__device__ __nv_bfloat16 g_ctxs[3][BATCH * LCTX * CTXD];
__device__ __nv_bfloat16 g_Was [3][HID * CTXD];
__device__ __nv_bfloat16 g_Wihs[3][G3H * XDIM];
__device__ __nv_bfloat16 g_embs[3][BATCH * TSTEPS * EMB];

// ---------------------------------------------------------------------------
// helpers
// ---------------------------------------------------------------------------
__device__ __forceinline__ uint32_t smem_u32(const void* p) {
    uint32_t a;
    asm("{ .reg .u64 t; cvta.to.shared.u64 t, %1; cvt.u32.u64 %0, t; }" : "=r"(a) : "l"(p));
    return a;
}

__device__ __forceinline__ void ldmx4(uint32_t& r0, uint32_t& r1, uint32_t& r2, uint32_t& r3,
                                      uint32_t addr) {
    asm volatile("ldmatrix.sync.aligned.m8n8.x4.shared.b16 {%0,%1,%2,%3}, [%4];"
                 : "=r"(r0), "=r"(r1), "=r"(r2), "=r"(r3) : "r"(addr));
}

__device__ __forceinline__ void mma16816(float* c, const uint32_t* a, const uint32_t* b) {
    asm volatile("mma.sync.aligned.m16n8k16.row.col.f32.bf16.bf16.f32 "
        "{%0,%1,%2,%3}, {%4,%5,%6,%7}, {%8,%9}, {%0,%1,%2,%3};"
        : "+f"(c[0]), "+f"(c[1]), "+f"(c[2]), "+f"(c[3])
        : "r"(a[0]), "r"(a[1]), "r"(a[2]), "r"(a[3]), "r"(b[0]), "r"(b[1]));
}

// ---------------------------------------------------------------------------
// Split fp32 -> 3x bf16 (hi, mid, lo): captures ~24 mantissa bits
// ---------------------------------------------------------------------------
__device__ __forceinline__ void split3(float x, __nv_bfloat16& h, __nv_bfloat16& m,
                                       __nv_bfloat16& l) {
    h = __float2bfloat16_rn(x);
    float r1 = x - __bfloat162float(h);     // exact
    m = __float2bfloat16_rn(r1);
    float r2 = r1 - __bfloat162float(m);    // exact
    l = __float2bfloat16_rn(r2);
}

__global__ void k_split(const float* __restrict__ s,
                        __nv_bfloat16* __restrict__ d0,
                        __nv_bfloat16* __restrict__ d1,
                        __nv_bfloat16* __restrict__ d2)
{
    int i = blockIdx.x * 256 + threadIdx.x;
    float4 v = ((const float4*)s)[i];
    __nv_bfloat16 h[4], m[4], l[4];
    float x[4] = {v.x, v.y, v.z, v.w};
#pragma unroll
    for (int q = 0; q < 4; q++) split3(x[q], h[q], m[q], l[q]);
    ((uint2*)d0)[i] = *(uint2*)h;
    ((uint2*)d1)[i] = *(uint2*)m;
    ((uint2*)d2)[i] = *(uint2*)l;
}

__global__ void k_split_emb(const float* __restrict__ emb, const int* __restrict__ tgt)
{
    int row = blockIdx.x;
    int tok = tgt[row];
    int c = threadIdx.x;   // 128 threads, 4 elems each
    float4 v = ((const float4*)(emb + (size_t)tok * EMB))[c];
    __nv_bfloat16 h[4], m[4], l[4];
    float x[4] = {v.x, v.y, v.z, v.w};
#pragma unroll
    for (int q = 0; q < 4; q++) split3(x[q], h[q], m[q], l[q]);
    ((uint2*)(g_embs[0] + (size_t)row * EMB))[c] = *(uint2*)h;
    ((uint2*)(g_embs[1] + (size_t)row * EMB))[c] = *(uint2*)m;
    ((uint2*)(g_embs[2] + (size_t)row * EMB))[c] = *(uint2*)l;
}

// ---------------------------------------------------------------------------
// mma.sync 6-term split-bf16 GEMM with fp32 register re-accumulation.
// C[M,N] = A @ B^T (+bias). Terms per k16, SMALL-FIRST order:
//   a2b2, a3b1, a1b3, a2b1, a1b2, a1b1 -> tensor acc t (zeroed per group),
// then t is folded into fp32 master accumulators with IEEE FADD. This bounds
// the tensor-core accumulator's truncation bias to ~1 full-magnitude add
// per k16 group (Ootomo-Yokota style), restoring ~fp32 GEMM accuracy.
// Tile 128x128, KT=32, 8 warps (2x4), 64x32 per warp. SMEM rows 80B padded.
// ---------------------------------------------------------------------------
#define ROWB 80
#define TILEB (128 * ROWB)
#define GSMEM (6 * TILEB)

__global__ void __launch_bounds__(256) k_mma_gemm(
    const __nv_bfloat16* __restrict__ A1, const __nv_bfloat16* __restrict__ A2,
    const __nv_bfloat16* __restrict__ A3, int lda,
    const __nv_bfloat16* __restrict__ B1, const __nv_bfloat16* __restrict__ B2,
    const __nv_bfloat16* __restrict__ B3, int ldb,
    int K, const float* __restrict__ bias,
    float* __restrict__ C, int ldc)
{
    extern __shared__ __align__(16) char smem[];
    char* tA1 = smem;
    char* tA2 = smem + TILEB;
    char* tA3 = smem + 2 * TILEB;
    char* tB1 = smem + 3 * TILEB;
    char* tB2 = smem + 4 * TILEB;
    char* tB3 = smem + 5 * TILEB;

    const int tid = threadIdx.x;
    const int w = tid >> 5, lane = tid & 31;
    const int wm = w >> 2, wn = w & 3;            // 2 x 4 warp grid
    const int m0 = blockIdx.y * 128, n0 = blockIdx.x * 128;

    const uint32_t sA1 = smem_u32(tA1), sA2 = smem_u32(tA2), sA3 = smem_u32(tA3);
    const uint32_t sB1 = smem_u32(tB1), sB2 = smem_u32(tB2), sB3 = smem_u32(tB3);

    const uint32_t aoff = (uint32_t)(wm * 64 + (lane & 15)) * ROWB + (lane >> 4) * 16;
    const uint32_t boff = (uint32_t)(wn * 32 + ((lane >> 4) & 1) * 8 + (lane & 7)) * ROWB
                        + ((lane >> 3) & 1) * 16;

    float master[4][4][4];
#pragma unroll
    for (int i = 0; i < 4; i++)
#pragma unroll
        for (int j = 0; j < 4; j++)
#pragma unroll
            for (int q = 0; q < 4; q++) master[i][j][q] = 0.f;

    const int r0 = tid >> 2, kc0 = tid & 3;
    const int r1 = (tid + 256) >> 2;

    for (int k0 = 0; k0 < K; k0 += 32) {
        {
            const __nv_bfloat16* p;
            p = A1 + (size_t)m0 * lda + k0;
            *(uint4*)(tA1 + r0 * ROWB + kc0 * 16) = *(const uint4*)(p + (size_t)r0 * lda + kc0 * 8);
            *(uint4*)(tA1 + r1 * ROWB + kc0 * 16) = *(const uint4*)(p + (size_t)r1 * lda + kc0 * 8);
            p = A2 + (size_t)m0 * lda + k0;
            *(uint4*)(tA2 + r0 * ROWB + kc0 * 16) = *(const uint4*)(p + (size_t)r0 * lda + kc0 * 8);
            *(uint4*)(tA2 + r1 * ROWB + kc0 * 16) = *(const uint4*)(p + (size_t)r1 * lda + kc0 * 8);
            p = A3 + (size_t)m0 * lda + k0;
            *(uint4*)(tA3 + r0 * ROWB + kc0 * 16) = *(const uint4*)(p + (size_t)r0 * lda + kc0 * 8);
            *(uint4*)(tA3 + r1 * ROWB + kc0 * 16) = *(const uint4*)(p + (size_t)r1 * lda + kc0 * 8);
            p = B1 + (size_t)n0 * ldb + k0;
            *(uint4*)(tB1 + r0 * ROWB + kc0 * 16) = *(const uint4*)(p + (size_t)r0 * ldb + kc0 * 8);
            *(uint4*)(tB1 + r1 * ROWB + kc0 * 16) = *(const uint4*)(p + (size_t)r1 * ldb + kc0 * 8);
            p = B2 + (size_t)n0 * ldb + k0;
            *(uint4*)(tB2 + r0 * ROWB + kc0 * 16) = *(const uint4*)(p + (size_t)r0 * ldb + kc0 * 8);
            *(uint4*)(tB2 + r1 * ROWB + kc0 * 16) = *(const uint4*)(p + (size_t)r1 * ldb + kc0 * 8);
            p = B3 + (size_t)n0 * ldb + k0;
            *(uint4*)(tB3 + r0 * ROWB + kc0 * 16) = *(const uint4*)(p + (size_t)r0 * ldb + kc0 * 8);
            *(uint4*)(tB3 + r1 * ROWB + kc0 * 16) = *(const uint4*)(p + (size_t)r1 * ldb + kc0 * 8);
        }
        __syncthreads();

#pragma unroll
        for (int k16 = 0; k16 < 2; k16++) {
            const uint32_t kadd = k16 * 32;
            uint32_t b1[8], b2[8], b3[8];
            ldmx4(b1[0], b1[1], b1[2], b1[3], sB1 + boff + kadd);
            ldmx4(b1[4], b1[5], b1[6], b1[7], sB1 + boff + kadd + 16 * ROWB);
            ldmx4(b2[0], b2[1], b2[2], b2[3], sB2 + boff + kadd);
            ldmx4(b2[4], b2[5], b2[6], b2[7], sB2 + boff + kadd + 16 * ROWB);
            ldmx4(b3[0], b3[1], b3[2], b3[3], sB3 + boff + kadd);
            ldmx4(b3[4], b3[5], b3[6], b3[7], sB3 + boff + kadd + 16 * ROWB);
#pragma unroll
            for (int mi = 0; mi < 4; mi++) {
                uint32_t a1[4], a2[4], a3[4];
                ldmx4(a1[0], a1[1], a1[2], a1[3], sA1 + aoff + mi * 16 * ROWB + kadd);
                ldmx4(a2[0], a2[1], a2[2], a2[3], sA2 + aoff + mi * 16 * ROWB + kadd);
                ldmx4(a3[0], a3[1], a3[2], a3[3], sA3 + aoff + mi * 16 * ROWB + kadd);
#pragma unroll
                for (int ni = 0; ni < 4; ni++) {
                    float t[4] = {0.f, 0.f, 0.f, 0.f};
                    // small terms first: the only full-magnitude truncating
                    // add inside the tensor acc is the final a1b1.
                    mma16816(t, a2, b2 + ni * 2);   // ~2^-16
                    mma16816(t, a3, b1 + ni * 2);   // ~2^-16
                    mma16816(t, a1, b3 + ni * 2);   // ~2^-16
                    mma16816(t, a2, b1 + ni * 2);   // ~2^-8
                    mma16816(t, a1, b2 + ni * 2);   // ~2^-8
                    mma16816(t, a1, b1 + ni * 2);   // ~1
#pragma unroll
                    for (int q = 0; q < 4; q++)
                        master[mi][ni][q] += t[q];  // IEEE RN accumulation
                }
            }
        }
        __syncthreads();
    }

    const int lr = lane >> 2, lc = (lane & 3) * 2;
#pragma unroll
    for (int mi = 0; mi < 4; mi++) {
#pragma unroll
        for (int ni = 0; ni < 4; ni++) {
            int n = n0 + wn * 32 + ni * 8 + lc;
            float bv0 = bias ? bias[n]     : 0.f;
            float bv1 = bias ? bias[n + 1] : 0.f;
            int mA = m0 + wm * 64 + mi * 16 + lr;
            float2 v0 = {master[mi][ni][0] + bv0, master[mi][ni][1] + bv1};
            float2 v1 = {master[mi][ni][2] + bv0, master[mi][ni][3] + bv1};
            *(float2*)(C + (size_t)mA * ldc + n)       = v0;
            *(float2*)(C + (size_t)(mA + 8) * ldc + n) = v1;
        }
    }
}

// ---------------------------------------------------------------------------
// K2: per step, 256 CTAs x 512 threads (unchanged from R9, passing).
// ---------------------------------------------------------------------------
#define PAD 68

__global__ void __launch_bounds__(512) k_step(
    const float* __restrict__ Whh,
    const float* __restrict__ bhh,
    const int* __restrict__ ctx_len)
{
    const int bx = blockIdx.x;
    const int tid = threadIdx.x;

    if (bx < 192) {
        __shared__ __align__(16) float Xs[32 * PAD];
        __shared__ __align__(16) float Ws[32 * PAD];
        const int kh = bx & 3;
        const int n0 = (bx >> 2) * 64;
        const float* A  = g_h + kh * 256;
        const float* Bw = Whh + kh * 256;

        const int tm = tid >> 4, tn = tid & 15;
        const int lrow = tid >> 3, lkc = tid & 7;

        float acc[2][4];
#pragma unroll
        for (int i = 0; i < 2; i++)
#pragma unroll
            for (int j = 0; j < 4; j++) acc[i][j] = 0.f;

        for (int k0 = 0; k0 < 256; k0 += 32) {
            float4 v = *(const float4*)(A + (size_t)lrow * HID + k0 + lkc * 4);
            Xs[(lkc * 4 + 0) * PAD + lrow] = v.x;
            Xs[(lkc * 4 + 1) * PAD + lrow] = v.y;
            Xs[(lkc * 4 + 2) * PAD + lrow] = v.z;
            Xs[(lkc * 4 + 3) * PAD + lrow] = v.w;
            float4 w = *(const float4*)(Bw + (size_t)(n0 + lrow) * HID + k0 + lkc * 4);
            Ws[(lkc * 4 + 0) * PAD + lrow] = w.x;
            Ws[(lkc * 4 + 1) * PAD + lrow] = w.y;
            Ws[(lkc * 4 + 2) * PAD + lrow] = w.z;
            Ws[(lkc * 4 + 3) * PAD + lrow] = w.w;
            __syncthreads();
#pragma unroll
            for (int kk = 0; kk < 32; kk++) {
                float a0 = Xs[kk * PAD + tm * 2];
                float a1 = Xs[kk * PAD + tm * 2 + 1];
                float b[4];
                *(float4*)b = *(const float4*)&Ws[kk * PAD + tn * 4];
#pragma unroll
                for (int j = 0; j < 4; j++) {
                    acc[0][j] = fmaf(a0, b[j], acc[0][j]);
                    acc[1][j] = fmaf(a1, b[j], acc[1][j]);
                }
            }
            __syncthreads();
        }

        float* dst = g_gh4[kh];
#pragma unroll
        for (int i = 0; i < 2; i++) {
            int m = tm * 2 + i;
            int n = n0 + tn * 4;
            float4 v;
            v.x = acc[i][0]; v.y = acc[i][1]; v.z = acc[i][2]; v.w = acc[i][3];
            if (kh == 0) {
                v.x += bhh[n]; v.y += bhh[n + 1]; v.z += bhh[n + 2]; v.w += bhh[n + 3];
            }
            *(float4*)(dst + (size_t)m * G3H + n) = v;
        }
        return;
    }

    // ---- attention CTA ----
    const int b = bx - 192;
    __shared__ __align__(16) float h_s[HID];
    __shared__ float attn_s[LCTX];

    ((float2*)h_s)[tid] = ((const float2*)(g_h + (size_t)b * HID))[tid];
    __syncthreads();

    const int w = tid >> 5, lane = tid & 31;
    const float4* h4 = (const float4*)h_s;
#pragma unroll
    for (int li = 0; li < 4; li++) {
        const int l = li * 16 + w;
        const float4* cw = (const float4*)(g_ctxW + ((size_t)b * LCTX + l) * HID);
        float s = 0.f;
#pragma unroll 8
        for (int i = lane; i < HID / 4; i += 32) {
            float4 a = h4[i], v = cw[i];
            s += a.x * v.x + a.y * v.y + a.z * v.z + a.w * v.w;
        }
#pragma unroll
        for (int off = 16; off > 0; off >>= 1)
            s += __shfl_xor_sync(0xffffffffu, s, off);
        if (lane == 0) attn_s[l] = s;
    }
    __syncthreads();

    if (tid < 32) {
        int len = ctx_len[b];
        float s0 = (tid < len)      ? attn_s[tid]      : -1e9f;
        float s1 = (tid + 32 < len) ? attn_s[tid + 32] : -1e9f;
        float m = fmaxf(s0, s1);
#pragma unroll
        for (int off = 16; off > 0; off >>= 1)
            m = fmaxf(m, __shfl_xor_sync(0xffffffffu, m, off));
        float e0 = __expf(s0 - m), e1 = __expf(s1 - m);
        float ss = e0 + e1;
#pragma unroll
        for (int off = 16; off > 0; off >>= 1)
            ss += __shfl_xor_sync(0xffffffffu, ss, off);
        attn_s[tid]      = e0 / ss;
        attn_s[tid + 32] = e1 / ss;
    }
    __syncthreads();

    float acc[6];
#pragma unroll
    for (int q = 0; q < 6; q++) acc[q] = 0.f;
    const float* base = g_ctxP + ((size_t)b * LCTX) * G3H + tid;
#pragma unroll 4
    for (int l = 0; l < LCTX; l++) {
        float a = attn_s[l];
        const float* row = base + (size_t)l * G3H;
#pragma unroll
        for (int q = 0; q < 6; q++)
            acc[q] = fmaf(a, row[q * 512], acc[q]);
    }
    float* dst = g_gxc + (size_t)b * G3H + tid;
#pragma unroll
    for (int q = 0; q < 6; q++) dst[q * 512] = acc[q];
}

// ---------------------------------------------------------------------------
// K1: pure GRU elementwise (unchanged from R9, passing).
// ---------------------------------------------------------------------------
__global__ void k_gru(int t,
                      const float* __restrict__ h0,
                      float* __restrict__ out)
{
    const int b = blockIdx.x;
    const int j = threadIdx.x * 4;

    if (t < 0) {
        *(float4*)(g_h + (size_t)b * HID + j) =
            *(const float4*)(h0 + (size_t)b * HID + j);
        return;
    }

    const float* gxe = g_gxe + (size_t)(b * TSTEPS + t) * G3H;
    const float* gxc = g_gxc + (size_t)b * G3H;
    float* hp = g_h + (size_t)b * HID;

    float hv[4];
#pragma unroll
    for (int q = 0; q < 4; q++) {
        int jj = j + q;
        float gxr = gxe[jj]           + gxc[jj];
        float gxz = gxe[HID + jj]     + gxc[HID + jj];
        float gxn = gxe[2 * HID + jj] + gxc[2 * HID + jj];
        float ghr = 0.f, ghz = 0.f, ghn = 0.f;
#pragma unroll
        for (int kh = 0; kh < 4; kh++) {
            const float* gh = g_gh4[kh] + (size_t)b * G3H;
            ghr += gh[jj];
            ghz += gh[HID + jj];
            ghn += gh[2 * HID + jj];
        }
        float r = 1.f / (1.f + __expf(-(gxr + ghr)));
        float z = 1.f / (1.f + __expf(-(gxz + ghz)));
        float n = tanhf(gxn + r * ghn);
        hv[q] = (1.f - z) * n + z * hp[jj];
    }
    *(float4*)(hp + j) = *(float4*)hv;
    *(float4*)(out + ((size_t)b * TSTEPS + t) * HID + j) = *(float4*)hv;
    if (t == TSTEPS - 1)
        *(float4*)(out + (size_t)BATCH * TSTEPS * HID + (size_t)b * HID + j) = *(float4*)hv;
}

// ---------------------------------------------------------------------------
extern "C" void kernel_launch(void* const* d_in, const int* in_sizes, int n_in,
                              void* d_out, int out_size)
{
    const int*   tgt     = (const int*)  d_in[0];
    const float* ctx     = (const float*)d_in[1];
    const float* h0      = (const float*)d_in[2];
    const int*   ctx_len = (const int*)  d_in[3];
    const float* emb     = (const float*)d_in[4];
    const float* Wa      = (const float*)d_in[5];
    const float* Wih     = (const float*)d_in[6];
    const float* Whh     = (const float*)d_in[7];
    const float* bih     = (const float*)d_in[8];
    const float* bhh     = (const float*)d_in[9];
    float* out = (float*)d_out;

    cudaFuncSetAttribute(k_mma_gemm, cudaFuncAttributeMaxDynamicSharedMemorySize, GSMEM);

    float* ctxW = nullptr; cudaGetSymbolAddress((void**)&ctxW, g_ctxW);
    float* ctxP = nullptr; cudaGetSymbolAddress((void**)&ctxP, g_ctxP);
    float* gxe  = nullptr; cudaGetSymbolAddress((void**)&gxe,  g_gxe);

    __nv_bfloat16 *ctxs, *Was, *Wihs, *embs;
    cudaGetSymbolAddress((void**)&ctxs, g_ctxs);
    cudaGetSymbolAddress((void**)&Was,  g_Was);
    cudaGetSymbolAddress((void**)&Wihs, g_Wihs);
    cudaGetSymbolAddress((void**)&embs, g_embs);
    const size_t CTXN = (size_t)BATCH * LCTX * CTXD;
    const size_t WAN  = (size_t)HID * CTXD;
    const size_t WIHN = (size_t)G3H * XDIM;
    const size_t EMBN = (size_t)BATCH * TSTEPS * EMB;
    __nv_bfloat16* c1 = ctxs; __nv_bfloat16* c2 = ctxs + CTXN; __nv_bfloat16* c3 = ctxs + 2 * CTXN;
    __nv_bfloat16* w1 = Was;  __nv_bfloat16* w2 = Was + WAN;   __nv_bfloat16* w3 = Was + 2 * WAN;
    __nv_bfloat16* i1 = Wihs; __nv_bfloat16* i2 = Wihs + WIHN; __nv_bfloat16* i3 = Wihs + 2 * WIHN;
    __nv_bfloat16* e1 = embs; __nv_bfloat16* e2 = embs + EMBN; __nv_bfloat16* e3 = embs + 2 * EMBN;

    // 3-way splits
    k_split<<<CTXN / 1024, 256>>>(ctx, c1, c2, c3);
    k_split<<<WAN  / 1024, 256>>>(Wa,  w1, w2, w3);
    k_split<<<WIHN / 1024, 256>>>(Wih, i1, i2, i3);
    k_split_emb<<<BATCH * TSTEPS, 128>>>(emb, tgt);

    // tensor-core precompute GEMMs (6-term split + fp32 re-accumulation)
    k_mma_gemm<<<dim3(G3H / 128, BATCH * TSTEPS / 128), 256, GSMEM>>>(
        e1, e2, e3, EMB, i1, i2, i3, XDIM, EMB, bih, gxe, G3H);
    k_mma_gemm<<<dim3(HID / 128, BATCH * LCTX / 128), 256, GSMEM>>>(
        c1, c2, c3, CTXD, w1, w2, w3, CTXD, CTXD, nullptr, ctxW, HID);
    k_mma_gemm<<<dim3(G3H / 128, BATCH * LCTX / 128), 256, GSMEM>>>(
        c1, c2, c3, CTXD, i1 + EMB, i2 + EMB, i3 + EMB, XDIM, CTXD, nullptr, ctxP, G3H);

    // Prologue: seed h = h0
    k_gru<<<BATCH, 256>>>(-1, h0, out);

    for (int t = 0; t < TSTEPS; t++) {
        k_step<<<256, 512>>>(Whh, bhh, ctx_len);   // scores/softmax/gxc + gh(t)
        k_gru<<<BATCH, 256>>>(t, h0, out);         // h(t) -> h(t+1), out
    }
}

// round 11
// speedup vs baseline: 4.2640x; 1.0835x over previous
#include <cuda_runtime.h>
#include <cuda_bf16.h>
#include <cstdint>

#define VOCAB 32000
#define EMB   512
#define HID   1024
#define CTXD  2048
#define BATCH 64
#define TSTEPS 64
#define LCTX  64
#define XDIM  (EMB + CTXD)   // 2560
#define G3H   (3 * HID)      // 3072

// ---------------------------------------------------------------------------
// Device-global scratch
// ---------------------------------------------------------------------------
__device__ float g_ctxW[BATCH * LCTX * HID];    // ctx @ Wa^T        [B*L, H]
__device__ float g_ctxP[BATCH * LCTX * G3H];    // ctx @ Wih_c^T     [B*L, 3H]
__device__ float g_gxe [BATCH * TSTEPS * G3H];  // emb @ Wih_e^T+bih [B*T, 3H]
__device__ float g_gxc [BATCH * G3H];           // attn-weighted ctxP
__device__ float g_gh4 [4][BATCH * G3H];        // K-split quarters of h @ Whh^T
__device__ float g_h   [BATCH * HID];           // hidden state

// bf16 3-way split buffers (hi / mid / lo)
__device__ __nv_bfloat16 g_ctxs[3][BATCH * LCTX * CTXD];
__device__ __nv_bfloat16 g_Was [3][HID * CTXD];
__device__ __nv_bfloat16 g_Wihs[3][G3H * XDIM];
__device__ __nv_bfloat16 g_embs[3][BATCH * TSTEPS * EMB];

// ---------------------------------------------------------------------------
// helpers
// ---------------------------------------------------------------------------
__device__ __forceinline__ uint32_t smem_u32(const void* p) {
    uint32_t a;
    asm("{ .reg .u64 t; cvta.to.shared.u64 t, %1; cvt.u32.u64 %0, t; }" : "=r"(a) : "l"(p));
    return a;
}

__device__ __forceinline__ void ldmx4(uint32_t& r0, uint32_t& r1, uint32_t& r2, uint32_t& r3,
                                      uint32_t addr) {
    asm volatile("ldmatrix.sync.aligned.m8n8.x4.shared.b16 {%0,%1,%2,%3}, [%4];"
                 : "=r"(r0), "=r"(r1), "=r"(r2), "=r"(r3) : "r"(addr));
}

__device__ __forceinline__ void mma16816(float* c, const uint32_t* a, const uint32_t* b) {
    asm volatile("mma.sync.aligned.m16n8k16.row.col.f32.bf16.bf16.f32 "
        "{%0,%1,%2,%3}, {%4,%5,%6,%7}, {%8,%9}, {%0,%1,%2,%3};"
        : "+f"(c[0]), "+f"(c[1]), "+f"(c[2]), "+f"(c[3])
        : "r"(a[0]), "r"(a[1]), "r"(a[2]), "r"(a[3]), "r"(b[0]), "r"(b[1]));
}

__device__ __forceinline__ void cp16(uint32_t dst, const void* src) {
    asm volatile("cp.async.cg.shared.global [%0], [%1], 16;" :: "r"(dst), "l"(src));
}
#define CP_COMMIT() asm volatile("cp.async.commit_group;" ::: "memory")
#define CP_WAIT1()  asm volatile("cp.async.wait_group 1;" ::: "memory")
#define CP_WAIT0()  asm volatile("cp.async.wait_group 0;" ::: "memory")

// ---------------------------------------------------------------------------
// Split fp32 -> 3x bf16 (hi, mid, lo): captures ~24 mantissa bits
// ---------------------------------------------------------------------------
__device__ __forceinline__ void split3(float x, __nv_bfloat16& h, __nv_bfloat16& m,
                                       __nv_bfloat16& l) {
    h = __float2bfloat16_rn(x);
    float r1 = x - __bfloat162float(h);     // exact
    m = __float2bfloat16_rn(r1);
    float r2 = r1 - __bfloat162float(m);    // exact
    l = __float2bfloat16_rn(r2);
}

__global__ void k_split(const float* __restrict__ s,
                        __nv_bfloat16* __restrict__ d0,
                        __nv_bfloat16* __restrict__ d1,
                        __nv_bfloat16* __restrict__ d2)
{
    int i = blockIdx.x * 256 + threadIdx.x;
    float4 v = ((const float4*)s)[i];
    __nv_bfloat16 h[4], m[4], l[4];
    float x[4] = {v.x, v.y, v.z, v.w};
#pragma unroll
    for (int q = 0; q < 4; q++) split3(x[q], h[q], m[q], l[q]);
    ((uint2*)d0)[i] = *(uint2*)h;
    ((uint2*)d1)[i] = *(uint2*)m;
    ((uint2*)d2)[i] = *(uint2*)l;
}

__global__ void k_split_emb(const float* __restrict__ emb, const int* __restrict__ tgt)
{
    int row = blockIdx.x;
    int tok = tgt[row];
    int c = threadIdx.x;   // 128 threads, 4 elems each
    float4 v = ((const float4*)(emb + (size_t)tok * EMB))[c];
    __nv_bfloat16 h[4], m[4], l[4];
    float x[4] = {v.x, v.y, v.z, v.w};
#pragma unroll
    for (int q = 0; q < 4; q++) split3(x[q], h[q], m[q], l[q]);
    ((uint2*)(g_embs[0] + (size_t)row * EMB))[c] = *(uint2*)h;
    ((uint2*)(g_embs[1] + (size_t)row * EMB))[c] = *(uint2*)m;
    ((uint2*)(g_embs[2] + (size_t)row * EMB))[c] = *(uint2*)l;
}

// ---------------------------------------------------------------------------
// mma.sync 6-term split-bf16 GEMM + fp32 re-accumulation (R10 numerics),
// now with cp.async 2-stage double buffering to hide global->smem latency.
// Tile 128x128, KT=32, 8 warps (2x4), 64x32 per warp. SMEM rows 80B padded.
// ---------------------------------------------------------------------------
#define ROWB 80
#define TILEB (128 * ROWB)        // 10240 B per operand tile
#define STAGEB (6 * TILEB)        // 61440 B per stage
#define GSMEM (2 * STAGEB)        // 122880 B total

__global__ void __launch_bounds__(256) k_mma_gemm(
    const __nv_bfloat16* __restrict__ A1, const __nv_bfloat16* __restrict__ A2,
    const __nv_bfloat16* __restrict__ A3, int lda,
    const __nv_bfloat16* __restrict__ B1, const __nv_bfloat16* __restrict__ B2,
    const __nv_bfloat16* __restrict__ B3, int ldb,
    int K, const float* __restrict__ bias,
    float* __restrict__ C, int ldc)
{
    extern __shared__ __align__(16) char smem[];

    const int tid = threadIdx.x;
    const int w = tid >> 5, lane = tid & 31;
    const int wm = w >> 2, wn = w & 3;            // 2 x 4 warp grid
    const int m0 = blockIdx.y * 128, n0 = blockIdx.x * 128;
    const uint32_t sbase = smem_u32(smem);

    const uint32_t aoff = (uint32_t)(wm * 64 + (lane & 15)) * ROWB + (lane >> 4) * 16;
    const uint32_t boff = (uint32_t)(wn * 32 + ((lane >> 4) & 1) * 8 + (lane & 7)) * ROWB
                        + ((lane >> 3) & 1) * 16;

    // loader lanes: each thread moves 2 rows x 16B per tile per chunk
    const int r0 = tid >> 2, kc0 = tid & 3;
    const int r1 = (tid + 256) >> 2;
    const uint32_t d0 = (uint32_t)r0 * ROWB + kc0 * 16;
    const uint32_t d1 = (uint32_t)r1 * ROWB + kc0 * 16;

    // issue cp.async loads for one chunk into one stage
    auto issue = [&](int stage, int k0) {
        const uint32_t sb = sbase + stage * STAGEB;
        const int ce = k0 + kc0 * 8;   // bf16 element offset of this thread's 16B
        cp16(sb + 0 * TILEB + d0, A1 + (size_t)(m0 + r0) * lda + ce);
        cp16(sb + 0 * TILEB + d1, A1 + (size_t)(m0 + r1) * lda + ce);
        cp16(sb + 1 * TILEB + d0, A2 + (size_t)(m0 + r0) * lda + ce);
        cp16(sb + 1 * TILEB + d1, A2 + (size_t)(m0 + r1) * lda + ce);
        cp16(sb + 2 * TILEB + d0, A3 + (size_t)(m0 + r0) * lda + ce);
        cp16(sb + 2 * TILEB + d1, A3 + (size_t)(m0 + r1) * lda + ce);
        cp16(sb + 3 * TILEB + d0, B1 + (size_t)(n0 + r0) * ldb + ce);
        cp16(sb + 3 * TILEB + d1, B1 + (size_t)(n0 + r1) * ldb + ce);
        cp16(sb + 4 * TILEB + d0, B2 + (size_t)(n0 + r0) * ldb + ce);
        cp16(sb + 4 * TILEB + d1, B2 + (size_t)(n0 + r1) * ldb + ce);
        cp16(sb + 5 * TILEB + d0, B3 + (size_t)(n0 + r0) * ldb + ce);
        cp16(sb + 5 * TILEB + d1, B3 + (size_t)(n0 + r1) * ldb + ce);
    };

    float master[4][4][4];
#pragma unroll
    for (int i = 0; i < 4; i++)
#pragma unroll
        for (int j = 0; j < 4; j++)
#pragma unroll
            for (int q = 0; q < 4; q++) master[i][j][q] = 0.f;

    const int NC = K / 32;

    issue(0, 0);
    CP_COMMIT();

    for (int c = 0; c < NC; c++) {
        if (c + 1 < NC) {
            issue((c + 1) & 1, (c + 1) * 32);
            CP_COMMIT();
            CP_WAIT1();
        } else {
            CP_WAIT0();
        }
        __syncthreads();

        const uint32_t sb = sbase + (c & 1) * STAGEB;
        const uint32_t sA1 = sb, sA2 = sb + TILEB, sA3 = sb + 2 * TILEB;
        const uint32_t sB1 = sb + 3 * TILEB, sB2 = sb + 4 * TILEB, sB3 = sb + 5 * TILEB;

#pragma unroll
        for (int k16 = 0; k16 < 2; k16++) {
            const uint32_t kadd = k16 * 32;
            uint32_t b1[8], b2[8], b3[8];
            ldmx4(b1[0], b1[1], b1[2], b1[3], sB1 + boff + kadd);
            ldmx4(b1[4], b1[5], b1[6], b1[7], sB1 + boff + kadd + 16 * ROWB);
            ldmx4(b2[0], b2[1], b2[2], b2[3], sB2 + boff + kadd);
            ldmx4(b2[4], b2[5], b2[6], b2[7], sB2 + boff + kadd + 16 * ROWB);
            ldmx4(b3[0], b3[1], b3[2], b3[3], sB3 + boff + kadd);
            ldmx4(b3[4], b3[5], b3[6], b3[7], sB3 + boff + kadd + 16 * ROWB);
#pragma unroll
            for (int mi = 0; mi < 4; mi++) {
                uint32_t a1[4], a2[4], a3[4];
                ldmx4(a1[0], a1[1], a1[2], a1[3], sA1 + aoff + mi * 16 * ROWB + kadd);
                ldmx4(a2[0], a2[1], a2[2], a2[3], sA2 + aoff + mi * 16 * ROWB + kadd);
                ldmx4(a3[0], a3[1], a3[2], a3[3], sA3 + aoff + mi * 16 * ROWB + kadd);
#pragma unroll
                for (int ni = 0; ni < 4; ni++) {
                    float t[4] = {0.f, 0.f, 0.f, 0.f};
                    // small terms first: only full-magnitude truncating add
                    // inside the tensor acc is the final a1b1.
                    mma16816(t, a2, b2 + ni * 2);   // ~2^-16
                    mma16816(t, a3, b1 + ni * 2);   // ~2^-16
                    mma16816(t, a1, b3 + ni * 2);   // ~2^-16
                    mma16816(t, a2, b1 + ni * 2);   // ~2^-8
                    mma16816(t, a1, b2 + ni * 2);   // ~2^-8
                    mma16816(t, a1, b1 + ni * 2);   // ~1
#pragma unroll
                    for (int q = 0; q < 4; q++)
                        master[mi][ni][q] += t[q];  // IEEE RN accumulation
                }
            }
        }
        __syncthreads();
    }

    const int lr = lane >> 2, lc = (lane & 3) * 2;
#pragma unroll
    for (int mi = 0; mi < 4; mi++) {
#pragma unroll
        for (int ni = 0; ni < 4; ni++) {
            int n = n0 + wn * 32 + ni * 8 + lc;
            float bv0 = bias ? bias[n]     : 0.f;
            float bv1 = bias ? bias[n + 1] : 0.f;
            int mA = m0 + wm * 64 + mi * 16 + lr;
            float2 v0 = {master[mi][ni][0] + bv0, master[mi][ni][1] + bv1};
            float2 v1 = {master[mi][ni][2] + bv0, master[mi][ni][3] + bv1};
            *(float2*)(C + (size_t)mA * ldc + n)       = v0;
            *(float2*)(C + (size_t)(mA + 8) * ldc + n) = v1;
        }
    }
}

// ---------------------------------------------------------------------------
// K2: per step, 256 CTAs x 512 threads (unchanged from R9/R10, passing).
// ---------------------------------------------------------------------------
#define PAD 68

__global__ void __launch_bounds__(512) k_step(
    const float* __restrict__ Whh,
    const float* __restrict__ bhh,
    const int* __restrict__ ctx_len)
{
    const int bx = blockIdx.x;
    const int tid = threadIdx.x;

    if (bx < 192) {
        __shared__ __align__(16) float Xs[32 * PAD];
        __shared__ __align__(16) float Ws[32 * PAD];
        const int kh = bx & 3;
        const int n0 = (bx >> 2) * 64;
        const float* A  = g_h + kh * 256;
        const float* Bw = Whh + kh * 256;

        const int tm = tid >> 4, tn = tid & 15;
        const int lrow = tid >> 3, lkc = tid & 7;

        float acc[2][4];
#pragma unroll
        for (int i = 0; i < 2; i++)
#pragma unroll
            for (int j = 0; j < 4; j++) acc[i][j] = 0.f;

        for (int k0 = 0; k0 < 256; k0 += 32) {
            float4 v = *(const float4*)(A + (size_t)lrow * HID + k0 + lkc * 4);
            Xs[(lkc * 4 + 0) * PAD + lrow] = v.x;
            Xs[(lkc * 4 + 1) * PAD + lrow] = v.y;
            Xs[(lkc * 4 + 2) * PAD + lrow] = v.z;
            Xs[(lkc * 4 + 3) * PAD + lrow] = v.w;
            float4 w = *(const float4*)(Bw + (size_t)(n0 + lrow) * HID + k0 + lkc * 4);
            Ws[(lkc * 4 + 0) * PAD + lrow] = w.x;
            Ws[(lkc * 4 + 1) * PAD + lrow] = w.y;
            Ws[(lkc * 4 + 2) * PAD + lrow] = w.z;
            Ws[(lkc * 4 + 3) * PAD + lrow] = w.w;
            __syncthreads();
#pragma unroll
            for (int kk = 0; kk < 32; kk++) {
                float a0 = Xs[kk * PAD + tm * 2];
                float a1 = Xs[kk * PAD + tm * 2 + 1];
                float b[4];
                *(float4*)b = *(const float4*)&Ws[kk * PAD + tn * 4];
#pragma unroll
                for (int j = 0; j < 4; j++) {
                    acc[0][j] = fmaf(a0, b[j], acc[0][j]);
                    acc[1][j] = fmaf(a1, b[j], acc[1][j]);
                }
            }
            __syncthreads();
        }

        float* dst = g_gh4[kh];
#pragma unroll
        for (int i = 0; i < 2; i++) {
            int m = tm * 2 + i;
            int n = n0 + tn * 4;
            float4 v;
            v.x = acc[i][0]; v.y = acc[i][1]; v.z = acc[i][2]; v.w = acc[i][3];
            if (kh == 0) {
                v.x += bhh[n]; v.y += bhh[n + 1]; v.z += bhh[n + 2]; v.w += bhh[n + 3];
            }
            *(float4*)(dst + (size_t)m * G3H + n) = v;
        }
        return;
    }

    // ---- attention CTA ----
    const int b = bx - 192;
    __shared__ __align__(16) float h_s[HID];
    __shared__ float attn_s[LCTX];

    ((float2*)h_s)[tid] = ((const float2*)(g_h + (size_t)b * HID))[tid];
    __syncthreads();

    const int w = tid >> 5, lane = tid & 31;
    const float4* h4 = (const float4*)h_s;
#pragma unroll
    for (int li = 0; li < 4; li++) {
        const int l = li * 16 + w;
        const float4* cw = (const float4*)(g_ctxW + ((size_t)b * LCTX + l) * HID);
        float s = 0.f;
#pragma unroll 8
        for (int i = lane; i < HID / 4; i += 32) {
            float4 a = h4[i], v = cw[i];
            s += a.x * v.x + a.y * v.y + a.z * v.z + a.w * v.w;
        }
#pragma unroll
        for (int off = 16; off > 0; off >>= 1)
            s += __shfl_xor_sync(0xffffffffu, s, off);
        if (lane == 0) attn_s[l] = s;
    }
    __syncthreads();

    if (tid < 32) {
        int len = ctx_len[b];
        float s0 = (tid < len)      ? attn_s[tid]      : -1e9f;
        float s1 = (tid + 32 < len) ? attn_s[tid + 32] : -1e9f;
        float m = fmaxf(s0, s1);
#pragma unroll
        for (int off = 16; off > 0; off >>= 1)
            m = fmaxf(m, __shfl_xor_sync(0xffffffffu, m, off));
        float e0 = __expf(s0 - m), e1 = __expf(s1 - m);
        float ss = e0 + e1;
#pragma unroll
        for (int off = 16; off > 0; off >>= 1)
            ss += __shfl_xor_sync(0xffffffffu, ss, off);
        attn_s[tid]      = e0 / ss;
        attn_s[tid + 32] = e1 / ss;
    }
    __syncthreads();

    float acc[6];
#pragma unroll
    for (int q = 0; q < 6; q++) acc[q] = 0.f;
    const float* base = g_ctxP + ((size_t)b * LCTX) * G3H + tid;
#pragma unroll 4
    for (int l = 0; l < LCTX; l++) {
        float a = attn_s[l];
        const float* row = base + (size_t)l * G3H;
#pragma unroll
        for (int q = 0; q < 6; q++)
            acc[q] = fmaf(a, row[q * 512], acc[q]);
    }
    float* dst = g_gxc + (size_t)b * G3H + tid;
#pragma unroll
    for (int q = 0; q < 6; q++) dst[q * 512] = acc[q];
}

// ---------------------------------------------------------------------------
// K1: pure GRU elementwise, parallelized 4x: grid = BATCH*4 CTAs x 256 thr,
// CTA (b, sl) handles h elements [sl*256, sl*256+256).
// ---------------------------------------------------------------------------
__global__ void k_gru(int t,
                      const float* __restrict__ h0,
                      float* __restrict__ out)
{
    const int bx = blockIdx.x;
    const int b = bx >> 2, sl = bx & 3;
    const int j = sl * 256 + threadIdx.x;

    if (t < 0) {
        g_h[(size_t)b * HID + j] = h0[(size_t)b * HID + j];
        return;
    }

    const float* gxe = g_gxe + (size_t)(b * TSTEPS + t) * G3H;
    const float* gxc = g_gxc + (size_t)b * G3H;
    float* hp = g_h + (size_t)b * HID;

    float gxr = gxe[j]           + gxc[j];
    float gxz = gxe[HID + j]     + gxc[HID + j];
    float gxn = gxe[2 * HID + j] + gxc[2 * HID + j];
    float ghr = 0.f, ghz = 0.f, ghn = 0.f;
#pragma unroll
    for (int kh = 0; kh < 4; kh++) {
        const float* gh = g_gh4[kh] + (size_t)b * G3H;
        ghr += gh[j];
        ghz += gh[HID + j];
        ghn += gh[2 * HID + j];
    }
    float r = 1.f / (1.f + __expf(-(gxr + ghr)));
    float z = 1.f / (1.f + __expf(-(gxz + ghz)));
    float n = tanhf(gxn + r * ghn);
    float hv = (1.f - z) * n + z * hp[j];

    hp[j] = hv;
    out[((size_t)b * TSTEPS + t) * HID + j] = hv;
    if (t == TSTEPS - 1)
        out[(size_t)BATCH * TSTEPS * HID + (size_t)b * HID + j] = hv;
}

// ---------------------------------------------------------------------------
extern "C" void kernel_launch(void* const* d_in, const int* in_sizes, int n_in,
                              void* d_out, int out_size)
{
    const int*   tgt     = (const int*)  d_in[0];
    const float* ctx     = (const float*)d_in[1];
    const float* h0      = (const float*)d_in[2];
    const int*   ctx_len = (const int*)  d_in[3];
    const float* emb     = (const float*)d_in[4];
    const float* Wa      = (const float*)d_in[5];
    const float* Wih     = (const float*)d_in[6];
    const float* Whh     = (const float*)d_in[7];
    const float* bih     = (const float*)d_in[8];
    const float* bhh     = (const float*)d_in[9];
    float* out = (float*)d_out;

    cudaFuncSetAttribute(k_mma_gemm, cudaFuncAttributeMaxDynamicSharedMemorySize, GSMEM);

    float* ctxW = nullptr; cudaGetSymbolAddress((void**)&ctxW, g_ctxW);
    float* ctxP = nullptr; cudaGetSymbolAddress((void**)&ctxP, g_ctxP);
    float* gxe  = nullptr; cudaGetSymbolAddress((void**)&gxe,  g_gxe);

    __nv_bfloat16 *ctxs, *Was, *Wihs, *embs;
    cudaGetSymbolAddress((void**)&ctxs, g_ctxs);
    cudaGetSymbolAddress((void**)&Was,  g_Was);
    cudaGetSymbolAddress((void**)&Wihs, g_Wihs);
    cudaGetSymbolAddress((void**)&embs, g_embs);
    const size_t CTXN = (size_t)BATCH * LCTX * CTXD;
    const size_t WAN  = (size_t)HID * CTXD;
    const size_t WIHN = (size_t)G3H * XDIM;
    const size_t EMBN = (size_t)BATCH * TSTEPS * EMB;
    __nv_bfloat16* c1 = ctxs; __nv_bfloat16* c2 = ctxs + CTXN; __nv_bfloat16* c3 = ctxs + 2 * CTXN;
    __nv_bfloat16* w1 = Was;  __nv_bfloat16* w2 = Was + WAN;   __nv_bfloat16* w3 = Was + 2 * WAN;
    __nv_bfloat16* i1 = Wihs; __nv_bfloat16* i2 = Wihs + WIHN; __nv_bfloat16* i3 = Wihs + 2 * WIHN;
    __nv_bfloat16* e1 = embs; __nv_bfloat16* e2 = embs + EMBN; __nv_bfloat16* e3 = embs + 2 * EMBN;

    // 3-way splits
    k_split<<<CTXN / 1024, 256>>>(ctx, c1, c2, c3);
    k_split<<<WAN  / 1024, 256>>>(Wa,  w1, w2, w3);
    k_split<<<WIHN / 1024, 256>>>(Wih, i1, i2, i3);
    k_split_emb<<<BATCH * TSTEPS, 128>>>(emb, tgt);

    // tensor-core precompute GEMMs (6-term split + fp32 re-accumulation,
    // cp.async double-buffered)
    k_mma_gemm<<<dim3(G3H / 128, BATCH * TSTEPS / 128), 256, GSMEM>>>(
        e1, e2, e3, EMB, i1, i2, i3, XDIM, EMB, bih, gxe, G3H);
    k_mma_gemm<<<dim3(HID / 128, BATCH * LCTX / 128), 256, GSMEM>>>(
        c1, c2, c3, CTXD, w1, w2, w3, CTXD, CTXD, nullptr, ctxW, HID);
    k_mma_gemm<<<dim3(G3H / 128, BATCH * LCTX / 128), 256, GSMEM>>>(
        c1, c2, c3, CTXD, i1 + EMB, i2 + EMB, i3 + EMB, XDIM, CTXD, nullptr, ctxP, G3H);

    // Prologue: seed h = h0
    k_gru<<<BATCH * 4, 256>>>(-1, h0, out);

    for (int t = 0; t < TSTEPS; t++) {
        k_step<<<256, 512>>>(Whh, bhh, ctx_len);   // scores/softmax/gxc + gh(t)
        k_gru<<<BATCH * 4, 256>>>(t, h0, out);     // h(t) -> h(t+1), out
    }
}